// round 7
// baseline (speedup 1.0000x reference)
#include <cuda_runtime.h>

#define NN_ 100000
#define NE_ 1600000
#define INF_ 128
#define HC_ 64
#define OC_ 32

// ---------------- scratch (static device globals; no allocation) ----------------
__device__ __align__(16) float  g_xl1[NN_ * HC_];   // x @ W1     (25.6 MB)
__device__ __align__(16) float  g_h1 [NN_ * HC_];   // relu(gat1) (25.6 MB)
__device__ __align__(16) float  g_xl2[NN_ * OC_];   // h @ W2     (12.8 MB)
__device__ float  g_as1[NN_ * 2];                   // layer1 per-node scores
__device__ float  g_ad1[NN_ * 2];
__device__ float  g_as2[NN_];
__device__ float  g_ad2[NN_];
__device__ int    g_deg[NN_];
__device__ int    g_ptr[NN_];
__device__ int    g_cur[NN_];
__device__ int    g_total;
__device__ int    g_esrc[NE_];
__device__ int    g_edst[NE_];
__device__ __align__(8) float2 g_eex1[NE_];         // exp(leaky(e)) layer1, 2 heads
__device__ float  g_eex2[NE_];

__device__ __forceinline__ float lrelu(float x) { return x > 0.f ? x : 0.2f * x; }

// ---------------- CSR build (no scans: bins in arbitrary order) ----------------
__global__ void prep_kernel() {
    int i = blockIdx.x * blockDim.x + threadIdx.x;
    if (i < NN_) g_deg[i] = 0;
    if (i == 0) g_total = 0;
}
__global__ void hist_kernel(const int* __restrict__ dst) {
    int i = blockIdx.x * blockDim.x + threadIdx.x;
    if (i < NE_) atomicAdd(&g_deg[dst[i]], 1);
}
__global__ void ptr_kernel() {
    int i = blockIdx.x * blockDim.x + threadIdx.x;
    if (i < NN_) {
        g_ptr[i] = atomicAdd(&g_total, g_deg[i]);  // bin offset (order irrelevant)
        g_cur[i] = 0;
    }
}
// scatter edges into bins; precompute per-edge exp(leaky(e)) for layer 1
__global__ void scatter_kernel(const int* __restrict__ src,
                               const int* __restrict__ dst) {
    int i = blockIdx.x * blockDim.x + threadIdx.x;
    if (i >= NE_) return;
    int s = src[i], d = dst[i];
    int p = g_ptr[d] + atomicAdd(&g_cur[d], 1);
    if (p < 0 || p >= NE_) return;               // defensive: never corrupt memory
    g_esrc[p] = s;
    g_edst[p] = d;
    float e0 = g_as1[s * 2 + 0] + g_ad1[d * 2 + 0];
    float e1 = g_as1[s * 2 + 1] + g_ad1[d * 2 + 1];
    g_eex1[p] = make_float2(__expf(lrelu(e0)), __expf(lrelu(e1)));
}

// ---------------- GEMM1: xl1[N][64] = x[N][128] @ W1[128][64] ----------------
// 512 threads = 16 warps = 16 nodes per block; lane owns 2 output cols.
__global__ void __launch_bounds__(512, 1)
gemm1_kernel(const float* __restrict__ x, const float* __restrict__ W1) {
    __shared__ float ws[INF_ * HC_];   // 32 KB
    __shared__ float xs[16 * INF_];    //  8 KB
    int t = threadIdx.x;
    int row0 = blockIdx.x * 16;

    for (int i = t; i < INF_ * HC_ / 4; i += 512)
        ((float4*)ws)[i] = ((const float4*)W1)[i];
    for (int i = t; i < 16 * INF_ / 4; i += 512) {
        int r = i / (INF_ / 4), k = i % (INF_ / 4);
        int gr = row0 + r;
        ((float4*)xs)[i] = (gr < NN_) ? ((const float4*)x)[gr * (INF_ / 4) + k]
                                      : make_float4(0.f, 0.f, 0.f, 0.f);
    }
    __syncthreads();

    int w = t >> 5, lane = t & 31;
    int n = row0 + w;
    if (n >= NN_) return;
    const float* xrow = &xs[w * INF_];
    float2 acc = make_float2(0.f, 0.f);
#pragma unroll 4
    for (int k = 0; k < INF_; k++) {
        float a = xrow[k];
        float2 wv = *(const float2*)&ws[k * HC_ + lane * 2];
        acc.x = fmaf(a, wv.x, acc.x);
        acc.y = fmaf(a, wv.y, acc.y);
    }
    ((float2*)g_xl1)[n * 32 + lane] = acc;
}

// ---------------- GEMM2: xl2[N][32] = h1[N][64] @ W2[64][32] ----------------
__global__ void __launch_bounds__(512, 1)
gemm2_kernel(const float* __restrict__ W2) {
    __shared__ float ws[HC_ * OC_];    // 8 KB
    __shared__ float xs[16 * HC_];     // 4 KB
    int t = threadIdx.x;
    int row0 = blockIdx.x * 16;

    for (int i = t; i < HC_ * OC_ / 4; i += 512)
        ((float4*)ws)[i] = ((const float4*)W2)[i];
    for (int i = t; i < 16 * HC_ / 4; i += 512) {
        int r = i / (HC_ / 4), k = i % (HC_ / 4);
        int gr = row0 + r;
        ((float4*)xs)[i] = (gr < NN_) ? ((const float4*)g_h1)[gr * (HC_ / 4) + k]
                                      : make_float4(0.f, 0.f, 0.f, 0.f);
    }
    __syncthreads();

    int w = t >> 5, lane = t & 31;
    int n = row0 + w;
    if (n >= NN_) return;
    const float* xrow = &xs[w * HC_];
    float acc = 0.f;
#pragma unroll 4
    for (int k = 0; k < HC_; k++)
        acc = fmaf(xrow[k], ws[k * OC_ + lane], acc);
    g_xl2[n * OC_ + lane] = acc;
}

// ---------------- per-node attention scores (dumb + clear) ----------------
__global__ void scores1_kernel(const float* __restrict__ asrc,
                               const float* __restrict__ adst) {
    int i = blockIdx.x * blockDim.x + threadIdx.x;
    if (i >= NN_ * 2) return;
    int n = i >> 1, h = i & 1;
    float as = 0.f, ad = 0.f;
    const float* row = &g_xl1[n * HC_ + h * 32];
#pragma unroll 8
    for (int c = 0; c < 32; c++) {
        float v = row[c];
        as = fmaf(v, __ldg(&asrc[h * 32 + c]), as);
        ad = fmaf(v, __ldg(&adst[h * 32 + c]), ad);
    }
    g_as1[n * 2 + h] = as;
    g_ad1[n * 2 + h] = ad;
}
__global__ void scores2_kernel(const float* __restrict__ asrc,
                               const float* __restrict__ adst) {
    int n = blockIdx.x * blockDim.x + threadIdx.x;
    if (n >= NN_) return;
    float as = 0.f, ad = 0.f;
    const float* row = &g_xl2[n * OC_];
#pragma unroll 8
    for (int c = 0; c < 32; c++) {
        float v = row[c];
        as = fmaf(v, __ldg(&asrc[c]), as);
        ad = fmaf(v, __ldg(&adst[c]), ad);
    }
    g_as2[n] = as;
    g_ad2[n] = ad;
}

// ---------------- layer-1 aggregation (warp per dst node) ----------------
// out_n = (Sigma_e ex_e * xl1[src_e]) / (Sigma_e ex_e), self loop analytic.
// Max-shift dropped: softmax is shift-invariant; scores are O(8) so exp finite.
__global__ void agg1_kernel(const float* __restrict__ b1) {
    int g = blockIdx.x * blockDim.x + threadIdx.x;
    int n = g >> 5, lane = g & 31;
    if (n >= NN_) return;
    float ex0 = __expf(lrelu(g_as1[n * 2 + 0] + g_ad1[n * 2 + 0]));  // self loop
    float ex1 = __expf(lrelu(g_as1[n * 2 + 1] + g_ad1[n * 2 + 1]));
    float den0 = ex0, den1 = ex1;
    const float2* xl = (const float2*)g_xl1;
    float2 v = xl[n * 32 + lane];
    bool h0 = lane < 16;                 // lanes 0-15: head0 channels, 16-31: head1
    float exm = h0 ? ex0 : ex1;
    float ax = exm * v.x, ay = exm * v.y;
    int st = g_ptr[n], de = g_deg[n];
    for (int j = 0; j < de; j++) {
        int s = g_esrc[st + j];          // broadcast
        float2 f = g_eex1[st + j];       // broadcast
        den0 += f.x; den1 += f.y;
        float2 w = xl[s * 32 + lane];    // 256B row gather
        float fm = h0 ? f.x : f.y;
        ax = fmaf(fm, w.x, ax);
        ay = fmaf(fm, w.y, ay);
    }
    float den = h0 ? den0 : den1;
    float inv = 1.f / (den + 1e-16f);
    float bx = b1[lane * 2], by = b1[lane * 2 + 1];
    float2 o;
    o.x = fmaxf(fmaf(ax, inv, bx), 0.f);   // bias + ReLU fused
    o.y = fmaxf(fmaf(ay, inv, by), 0.f);
    ((float2*)g_h1)[n * 32 + lane] = o;
}

// ---------------- layer-2 edge exp + aggregation ----------------
__global__ void exp2_kernel() {
    int p = blockIdx.x * blockDim.x + threadIdx.x;
    if (p >= NE_) return;
    g_eex2[p] = __expf(lrelu(g_as2[g_esrc[p]] + g_ad2[g_edst[p]]));
}
__global__ void agg2_kernel(const float* __restrict__ b2, float* __restrict__ out) {
    int g = blockIdx.x * blockDim.x + threadIdx.x;
    int n = g >> 5, lane = g & 31;
    if (n >= NN_) return;
    float ex = __expf(lrelu(g_as2[n] + g_ad2[n]));   // self loop
    float den = ex;
    float acc = ex * g_xl2[n * OC_ + lane];
    int st = g_ptr[n], de = g_deg[n];
    for (int j = 0; j < de; j++) {
        int s = g_esrc[st + j];          // broadcast
        float f = g_eex2[st + j];        // broadcast
        den += f;
        acc = fmaf(f, g_xl2[s * OC_ + lane], acc);   // 128B row gather
    }
    out[n * OC_ + lane] = acc / (den + 1e-16f) + b2[lane];
}

// ---------------- launch ----------------
extern "C" void kernel_launch(void* const* d_in, const int* in_sizes, int n_in,
                              void* d_out, int out_size) {
    // size-keyed input remap with positional fallback
    const float* x = 0; const int* ei = 0;
    const float* W1 = 0; const float* W2 = 0;
    const float* a64[3] = {0, 0, 0}; int n64 = 0;
    const float* a32[3] = {0, 0, 0}; int n32 = 0;
    for (int i = 0; i < n_in; i++) {
        int sz = in_sizes[i];
        if      (sz == NN_ * INF_) x  = (const float*)d_in[i];
        else if (sz == 2 * NE_)    ei = (const int*)  d_in[i];
        else if (sz == INF_ * HC_) W1 = (const float*)d_in[i];
        else if (sz == HC_ * OC_)  W2 = (const float*)d_in[i];
        else if (sz == HC_) { if (n64 < 3) a64[n64++] = (const float*)d_in[i]; }
        else if (sz == OC_) { if (n32 < 3) a32[n32++] = (const float*)d_in[i]; }
    }
    if (!x)  x  = (const float*)d_in[0];
    if (!ei) ei = (const int*)  d_in[1];
    if (!W1) W1 = (const float*)d_in[2];
    if (!W2) W2 = (const float*)d_in[6];
    const float* as1 = a64[0] ? a64[0] : (const float*)d_in[3];
    const float* ad1 = a64[1] ? a64[1] : (const float*)d_in[4];
    const float* b1  = a64[2] ? a64[2] : (const float*)d_in[5];
    const float* as2 = a32[0] ? a32[0] : (const float*)d_in[7];
    const float* ad2 = a32[1] ? a32[1] : (const float*)d_in[8];
    const float* b2  = a32[2] ? a32[2] : (const float*)d_in[9];
    float* out = (float*)d_out;

    const int* srcp = ei;
    const int* dstp = ei + NE_;

    const int NB  = (NN_ + 255) / 256;         // node blocks
    const int EB  = (NE_ + 255) / 256;         // edge blocks
    const int GB  = (NN_ + 15) / 16;           // 6250 gemm blocks (16 nodes each)
    const int WB  = (NN_ * 32 + 255) / 256;    // 12500 warp-per-node blocks

    prep_kernel<<<NB, 256>>>();
    hist_kernel<<<EB, 256>>>(dstp);
    ptr_kernel<<<NB, 256>>>();

    gemm1_kernel<<<GB, 512>>>(x, W1);
    scores1_kernel<<<(2 * NN_ + 255) / 256, 256>>>(as1, ad1);
    scatter_kernel<<<EB, 256>>>(srcp, dstp);
    agg1_kernel<<<WB, 256>>>(b1);

    gemm2_kernel<<<GB, 512>>>(W2);
    scores2_kernel<<<NB, 256>>>(as2, ad2);
    exp2_kernel<<<EB, 256>>>();
    agg2_kernel<<<WB, 256>>>(b2, out);

    (void)n_in; (void)out_size;
}

// round 8
// speedup vs baseline: 1.3385x; 1.3385x over previous
#include <cuda_runtime.h>

#define NN_ 100000
#define NE_ 1600000
#define INF_ 128
#define HC_ 64
#define OC_ 32

// ---------------- scratch (static device globals; no allocation) ----------------
__device__ __align__(16) float  g_xl1[NN_ * HC_];   // x @ W1     (25.6 MB)
__device__ __align__(16) float  g_h1 [NN_ * HC_];   // relu(gat1) (25.6 MB)
__device__ __align__(16) float  g_xl2[NN_ * OC_];   // h @ W2     (12.8 MB)
__device__ float  g_as1[NN_ * 2];                   // layer1 per-node scores
__device__ float  g_ad1[NN_ * 2];
__device__ float  g_as2[NN_];
__device__ float  g_ad2[NN_];
__device__ int    g_deg[NN_];
__device__ int    g_ptr[NN_];
__device__ int    g_cur[NN_];
__device__ int    g_total;
__device__ int    g_esrc[NE_];
__device__ int    g_edst[NE_];
__device__ __align__(8) float2 g_eex1[NE_];         // exp(leaky(e)) layer1, 2 heads
__device__ float  g_eex2[NE_];

__device__ __forceinline__ float lrelu(float x) { return x > 0.f ? x : 0.2f * x; }

// ---------------- CSR build (no scans: bins in arbitrary order) ----------------
__global__ void prep_kernel() {
    int i = blockIdx.x * blockDim.x + threadIdx.x;
    if (i < NN_) g_deg[i] = 0;
    if (i == 0) g_total = 0;
}
__global__ void hist_kernel(const int* __restrict__ dst) {
    int i = blockIdx.x * blockDim.x + threadIdx.x;
    if (i < NE_) atomicAdd(&g_deg[dst[i]], 1);
}
__global__ void ptr_kernel() {
    int i = blockIdx.x * blockDim.x + threadIdx.x;
    if (i < NN_) {
        g_ptr[i] = atomicAdd(&g_total, g_deg[i]);  // bin offset (order irrelevant)
        g_cur[i] = 0;
    }
}
// scatter edges into bins; precompute per-edge exp(leaky(e)) for layer 1
__global__ void scatter_kernel(const int* __restrict__ src,
                               const int* __restrict__ dst) {
    int i = blockIdx.x * blockDim.x + threadIdx.x;
    if (i >= NE_) return;
    int s = src[i], d = dst[i];
    int p = g_ptr[d] + atomicAdd(&g_cur[d], 1);
    if (p < 0 || p >= NE_) return;               // defensive: never corrupt memory
    g_esrc[p] = s;
    g_edst[p] = d;
    float e0 = g_as1[s * 2 + 0] + g_ad1[d * 2 + 0];
    float e1 = g_as1[s * 2 + 1] + g_ad1[d * 2 + 1];
    g_eex1[p] = make_float2(__expf(lrelu(e0)), __expf(lrelu(e1)));
}

// ---------------- GEMM1 + scores1 fused ----------------
// xl1[N][64] = x[N][128] @ W1[128][64]; scores via epilogue shfl reduction.
// 256 threads: tx=t%8 owns 8 cols, ty=t/8 owns 4 rows (128-row tile).
// A tile stored k-major (xs[k][row]) -> 1 LDS.128 per k loads 4 rows; all
// compute-loop LDS conflict-free (uniform-k B broadcast, 16B-strided A).
__global__ void __launch_bounds__(256, 1)
gemm1_kernel(const float* __restrict__ x, const float* __restrict__ W1,
             const float* __restrict__ as, const float* __restrict__ ad) {
    __shared__ float ws[INF_ * HC_];   // 32 KB, [k][c]
    __shared__ float xs[16 * 128];     //  8 KB, [k_local][row]
    __shared__ float sa[HC_], sd[HC_];
    int t = threadIdx.x;
    int tx = t & 7, ty = t >> 3;
    int row0 = blockIdx.x * 128;

    if (t < HC_) { sa[t] = as[t]; sd[t] = ad[t]; }
    for (int i = t; i < INF_ * HC_ / 4; i += 256)
        ((float4*)ws)[i] = ((const float4*)W1)[i];

    float acc[4][8];
#pragma unroll
    for (int a = 0; a < 4; a++)
#pragma unroll
        for (int b = 0; b < 8; b++) acc[a][b] = 0.f;

    for (int c = 0; c < 8; c++) {                // 8 chunks of 16 k
        __syncthreads();
        for (int idx = t; idx < 512; idx += 256) {
            int r = idx >> 2, q = idx & 3;       // q: float4 within chunk
            int gr = row0 + r;
            float4 v = (gr < NN_) ? ((const float4*)x)[gr * 32 + c * 4 + q]
                                  : make_float4(0.f, 0.f, 0.f, 0.f);
            xs[(4 * q + 0) * 128 + r] = v.x;     // transpose into [k][row]
            xs[(4 * q + 1) * 128 + r] = v.y;
            xs[(4 * q + 2) * 128 + r] = v.z;
            xs[(4 * q + 3) * 128 + r] = v.w;
        }
        __syncthreads();
#pragma unroll
        for (int k = 0; k < 16; k++) {
            float4 a4 = *(const float4*)&xs[k * 128 + ty * 4];    // 4 rows
            const float* wr = &ws[(c * 16 + k) * HC_ + tx * 8];
            float4 b0 = *(const float4*)&wr[0];
            float4 b1 = *(const float4*)&wr[4];
            float av[4] = {a4.x, a4.y, a4.z, a4.w};
#pragma unroll
            for (int nn = 0; nn < 4; nn++) {
                float a = av[nn];
                acc[nn][0] = fmaf(a, b0.x, acc[nn][0]);
                acc[nn][1] = fmaf(a, b0.y, acc[nn][1]);
                acc[nn][2] = fmaf(a, b0.z, acc[nn][2]);
                acc[nn][3] = fmaf(a, b0.w, acc[nn][3]);
                acc[nn][4] = fmaf(a, b1.x, acc[nn][4]);
                acc[nn][5] = fmaf(a, b1.y, acc[nn][5]);
                acc[nn][6] = fmaf(a, b1.z, acc[nn][6]);
                acc[nn][7] = fmaf(a, b1.w, acc[nn][7]);
            }
        }
    }
    // epilogue: store + fused scores (cols tx*8..tx*8+7 are within one head)
#pragma unroll
    for (int nn = 0; nn < 4; nn++) {
        int n = row0 + ty * 4 + nn;
        float pas = 0.f, pad = 0.f;
#pragma unroll
        for (int cc = 0; cc < 8; cc++) {
            pas = fmaf(acc[nn][cc], sa[tx * 8 + cc], pas);
            pad = fmaf(acc[nn][cc], sd[tx * 8 + cc], pad);
        }
        pas += __shfl_xor_sync(0xffffffffu, pas, 1);
        pas += __shfl_xor_sync(0xffffffffu, pas, 2);
        pad += __shfl_xor_sync(0xffffffffu, pad, 1);
        pad += __shfl_xor_sync(0xffffffffu, pad, 2);
        if (n < NN_) {
            *(float4*)&g_xl1[n * HC_ + tx * 8] =
                make_float4(acc[nn][0], acc[nn][1], acc[nn][2], acc[nn][3]);
            *(float4*)&g_xl1[n * HC_ + tx * 8 + 4] =
                make_float4(acc[nn][4], acc[nn][5], acc[nn][6], acc[nn][7]);
            if (tx == 0 || tx == 4) {            // tx<4: head0, tx>=4: head1
                int h = tx >> 2;
                g_as1[n * 2 + h] = pas;
                g_ad1[n * 2 + h] = pad;
            }
        }
    }
}

// ---------------- GEMM2 + scores2 fused ----------------
// xl2[N][32] = h1[N][64] @ W2[64][32]. tx=t%4 owns 8 cols, ty=t/4 owns 2 rows.
__global__ void __launch_bounds__(256, 1)
gemm2_kernel(const float* __restrict__ W2,
             const float* __restrict__ as, const float* __restrict__ ad) {
    __shared__ float ws[HC_ * OC_];    //  8 KB, [k][c]
    __shared__ float xs[HC_ * 128];    // 32 KB, [k][row]
    __shared__ float sa[OC_], sd[OC_];
    int t = threadIdx.x;
    int tx = t & 3, ty = t >> 2;
    int row0 = blockIdx.x * 128;

    if (t < OC_) { sa[t] = as[t]; sd[t] = ad[t]; }
    for (int i = t; i < HC_ * OC_ / 4; i += 256)
        ((float4*)ws)[i] = ((const float4*)W2)[i];
    for (int idx = t; idx < 128 * 16; idx += 256) {
        int r = idx >> 4, q = idx & 15;
        int gr = row0 + r;
        float4 v = (gr < NN_) ? ((const float4*)g_h1)[gr * 16 + q]
                              : make_float4(0.f, 0.f, 0.f, 0.f);
        xs[(4 * q + 0) * 128 + r] = v.x;
        xs[(4 * q + 1) * 128 + r] = v.y;
        xs[(4 * q + 2) * 128 + r] = v.z;
        xs[(4 * q + 3) * 128 + r] = v.w;
    }
    __syncthreads();

    float acc[2][8];
#pragma unroll
    for (int a = 0; a < 2; a++)
#pragma unroll
        for (int b = 0; b < 8; b++) acc[a][b] = 0.f;

#pragma unroll 8
    for (int k = 0; k < HC_; k++) {
        float2 a2 = *(const float2*)&xs[k * 128 + ty * 2];
        const float* wr = &ws[k * OC_ + tx * 8];
        float4 b0 = *(const float4*)&wr[0];
        float4 b1 = *(const float4*)&wr[4];
        float av[2] = {a2.x, a2.y};
#pragma unroll
        for (int nn = 0; nn < 2; nn++) {
            float a = av[nn];
            acc[nn][0] = fmaf(a, b0.x, acc[nn][0]);
            acc[nn][1] = fmaf(a, b0.y, acc[nn][1]);
            acc[nn][2] = fmaf(a, b0.z, acc[nn][2]);
            acc[nn][3] = fmaf(a, b0.w, acc[nn][3]);
            acc[nn][4] = fmaf(a, b1.x, acc[nn][4]);
            acc[nn][5] = fmaf(a, b1.y, acc[nn][5]);
            acc[nn][6] = fmaf(a, b1.z, acc[nn][6]);
            acc[nn][7] = fmaf(a, b1.w, acc[nn][7]);
        }
    }
#pragma unroll
    for (int nn = 0; nn < 2; nn++) {
        int n = row0 + ty * 2 + nn;
        float pas = 0.f, pad = 0.f;
#pragma unroll
        for (int cc = 0; cc < 8; cc++) {
            pas = fmaf(acc[nn][cc], sa[tx * 8 + cc], pas);
            pad = fmaf(acc[nn][cc], sd[tx * 8 + cc], pad);
        }
        pas += __shfl_xor_sync(0xffffffffu, pas, 1);
        pas += __shfl_xor_sync(0xffffffffu, pas, 2);
        pad += __shfl_xor_sync(0xffffffffu, pad, 1);
        pad += __shfl_xor_sync(0xffffffffu, pad, 2);
        if (n < NN_) {
            *(float4*)&g_xl2[n * OC_ + tx * 8] =
                make_float4(acc[nn][0], acc[nn][1], acc[nn][2], acc[nn][3]);
            *(float4*)&g_xl2[n * OC_ + tx * 8 + 4] =
                make_float4(acc[nn][4], acc[nn][5], acc[nn][6], acc[nn][7]);
            if (tx == 0) { g_as2[n] = pas; g_ad2[n] = pad; }
        }
    }
}

// ---------------- layer-1 aggregation (warp per dst node) ----------------
// out_n = (Sigma_e ex_e * xl1[src_e]) / (Sigma_e ex_e), self loop analytic.
// Max-shift dropped: softmax is shift-invariant; scores are O(8) so exp finite.
__global__ void agg1_kernel(const float* __restrict__ b1) {
    int g = blockIdx.x * blockDim.x + threadIdx.x;
    int n = g >> 5, lane = g & 31;
    if (n >= NN_) return;
    float ex0 = __expf(lrelu(g_as1[n * 2 + 0] + g_ad1[n * 2 + 0]));  // self loop
    float ex1 = __expf(lrelu(g_as1[n * 2 + 1] + g_ad1[n * 2 + 1]));
    float den0 = ex0, den1 = ex1;
    const float2* xl = (const float2*)g_xl1;
    float2 v = xl[n * 32 + lane];
    bool h0 = lane < 16;                 // lanes 0-15: head0 channels, 16-31: head1
    float exm = h0 ? ex0 : ex1;
    float ax = exm * v.x, ay = exm * v.y;
    int st = g_ptr[n], de = g_deg[n];
    for (int j = 0; j < de; j++) {
        int s = g_esrc[st + j];          // broadcast
        float2 f = g_eex1[st + j];       // broadcast
        den0 += f.x; den1 += f.y;
        float2 w = xl[s * 32 + lane];    // 256B row gather
        float fm = h0 ? f.x : f.y;
        ax = fmaf(fm, w.x, ax);
        ay = fmaf(fm, w.y, ay);
    }
    float den = h0 ? den0 : den1;
    float inv = 1.f / (den + 1e-16f);
    float bx = b1[lane * 2], by = b1[lane * 2 + 1];
    float2 o;
    o.x = fmaxf(fmaf(ax, inv, bx), 0.f);   // bias + ReLU fused
    o.y = fmaxf(fmaf(ay, inv, by), 0.f);
    ((float2*)g_h1)[n * 32 + lane] = o;
}

// ---------------- layer-2 edge exp + aggregation ----------------
__global__ void exp2_kernel() {
    int p = blockIdx.x * blockDim.x + threadIdx.x;
    if (p >= NE_) return;
    g_eex2[p] = __expf(lrelu(g_as2[g_esrc[p]] + g_ad2[g_edst[p]]));
}
__global__ void agg2_kernel(const float* __restrict__ b2, float* __restrict__ out) {
    int g = blockIdx.x * blockDim.x + threadIdx.x;
    int n = g >> 5, lane = g & 31;
    if (n >= NN_) return;
    float ex = __expf(lrelu(g_as2[n] + g_ad2[n]));   // self loop
    float den = ex;
    float acc = ex * g_xl2[n * OC_ + lane];
    int st = g_ptr[n], de = g_deg[n];
    for (int j = 0; j < de; j++) {
        int s = g_esrc[st + j];          // broadcast
        float f = g_eex2[st + j];        // broadcast
        den += f;
        acc = fmaf(f, g_xl2[s * OC_ + lane], acc);   // 128B row gather
    }
    out[n * OC_ + lane] = acc / (den + 1e-16f) + b2[lane];
}

// ---------------- launch ----------------
extern "C" void kernel_launch(void* const* d_in, const int* in_sizes, int n_in,
                              void* d_out, int out_size) {
    // size-keyed input remap with positional fallback
    const float* x = 0; const int* ei = 0;
    const float* W1 = 0; const float* W2 = 0;
    const float* a64[3] = {0, 0, 0}; int n64 = 0;
    const float* a32[3] = {0, 0, 0}; int n32 = 0;
    for (int i = 0; i < n_in; i++) {
        int sz = in_sizes[i];
        if      (sz == NN_ * INF_) x  = (const float*)d_in[i];
        else if (sz == 2 * NE_)    ei = (const int*)  d_in[i];
        else if (sz == INF_ * HC_) W1 = (const float*)d_in[i];
        else if (sz == HC_ * OC_)  W2 = (const float*)d_in[i];
        else if (sz == HC_) { if (n64 < 3) a64[n64++] = (const float*)d_in[i]; }
        else if (sz == OC_) { if (n32 < 3) a32[n32++] = (const float*)d_in[i]; }
    }
    if (!x)  x  = (const float*)d_in[0];
    if (!ei) ei = (const int*)  d_in[1];
    if (!W1) W1 = (const float*)d_in[2];
    if (!W2) W2 = (const float*)d_in[6];
    const float* as1 = a64[0] ? a64[0] : (const float*)d_in[3];
    const float* ad1 = a64[1] ? a64[1] : (const float*)d_in[4];
    const float* b1  = a64[2] ? a64[2] : (const float*)d_in[5];
    const float* as2 = a32[0] ? a32[0] : (const float*)d_in[7];
    const float* ad2 = a32[1] ? a32[1] : (const float*)d_in[8];
    const float* b2  = a32[2] ? a32[2] : (const float*)d_in[9];
    float* out = (float*)d_out;

    const int* srcp = ei;
    const int* dstp = ei + NE_;

    const int NB  = (NN_ + 255) / 256;         // node blocks
    const int EB  = (NE_ + 255) / 256;         // edge blocks
    const int GB  = (NN_ + 127) / 128;         // 782 gemm blocks (128 rows each)
    const int WB  = (NN_ * 32 + 255) / 256;    // 12500 warp-per-node blocks

    prep_kernel<<<NB, 256>>>();
    hist_kernel<<<EB, 256>>>(dstp);
    ptr_kernel<<<NB, 256>>>();

    gemm1_kernel<<<GB, 256>>>(x, W1, as1, ad1);
    scatter_kernel<<<EB, 256>>>(srcp, dstp);
    agg1_kernel<<<WB, 256>>>(b1);

    gemm2_kernel<<<GB, 256>>>(W2, as2, ad2);
    exp2_kernel<<<EB, 256>>>();
    agg2_kernel<<<WB, 256>>>(b2, out);

    (void)n_in; (void)out_size;
}

// round 9
// speedup vs baseline: 1.4342x; 1.0715x over previous
#include <cuda_runtime.h>

#define NN_ 100000
#define NE_ 1600000
#define INF_ 128
#define HC_ 64
#define OC_ 32

// ---------------- scratch (static device globals; no allocation) ----------------
__device__ __align__(16) float  g_xl1[NN_ * HC_];   // x @ W1     (25.6 MB)
__device__ __align__(16) float  g_h1 [NN_ * HC_];   // relu(gat1) (25.6 MB)
__device__ __align__(16) float  g_xl2[NN_ * OC_];   // h @ W2     (12.8 MB)
__device__ float  g_as1[NN_ * 2];                   // layer1 per-node scores
__device__ float  g_ad1[NN_ * 2];
__device__ float  g_as2[NN_];
__device__ float  g_ad2[NN_];
__device__ int    g_deg[NN_];
__device__ int    g_ptr[NN_];
__device__ int    g_cur[NN_];
__device__ int    g_total;
__device__ int    g_esrc[NE_];
__device__ int    g_edst[NE_];
__device__ __align__(8) float2 g_eex1[NE_];         // exp(leaky(e)) layer1, 2 heads
__device__ float  g_eex2[NE_];

__device__ __forceinline__ float lrelu(float x) { return x > 0.f ? x : 0.2f * x; }

typedef unsigned long long ull;
__device__ __forceinline__ ull pk2(float x, float y) {
    ull r; asm("mov.b64 %0,{%1,%2};" : "=l"(r) : "f"(x), "f"(y)); return r;
}
__device__ __forceinline__ void up2(ull v, float& x, float& y) {
    asm("mov.b64 {%0,%1},%2;" : "=f"(x), "=f"(y) : "l"(v));
}
// packed fp32x2 FMA (FFMA2): d.lo=fma(a.lo,b.lo,c.lo), d.hi likewise
__device__ __forceinline__ ull f2fma(ull a, ull b, ull c) {
    ull d; asm("fma.rn.f32x2 %0,%1,%2,%3;" : "=l"(d) : "l"(a), "l"(b), "l"(c)); return d;
}

// ---------------- CSR build (no scans: bins in arbitrary order) ----------------
__global__ void prep_kernel() {
    int i = blockIdx.x * blockDim.x + threadIdx.x;
    if (i < NN_) g_deg[i] = 0;
    if (i == 0) g_total = 0;
}
__global__ void hist_kernel(const int* __restrict__ dst) {
    int i = blockIdx.x * blockDim.x + threadIdx.x;
    if (i < NE_) atomicAdd(&g_deg[dst[i]], 1);
}
__global__ void ptr_kernel() {
    int i = blockIdx.x * blockDim.x + threadIdx.x;
    if (i < NN_) {
        g_ptr[i] = atomicAdd(&g_total, g_deg[i]);  // bin offset (order irrelevant)
        g_cur[i] = 0;
    }
}
// scatter edges into bins; precompute per-edge exp(leaky(e)) for layer 1
__global__ void scatter_kernel(const int* __restrict__ src,
                               const int* __restrict__ dst) {
    int i = blockIdx.x * blockDim.x + threadIdx.x;
    if (i >= NE_) return;
    int s = src[i], d = dst[i];
    int p = g_ptr[d] + atomicAdd(&g_cur[d], 1);
    if (p < 0 || p >= NE_) return;               // defensive: never corrupt memory
    g_esrc[p] = s;
    g_edst[p] = d;
    float e0 = g_as1[s * 2 + 0] + g_ad1[d * 2 + 0];
    float e1 = g_as1[s * 2 + 1] + g_ad1[d * 2 + 1];
    g_eex1[p] = make_float2(__expf(lrelu(e0)), __expf(lrelu(e1)));
}

// ---------------- GEMM1 + scores1 fused (FFMA2, 8x8 register block) ----------
// xl1[N][64] = x[N][128] @ W1[128][64]; scores fused in epilogue.
// 256 threads: tx=t&7 owns 8 cols, ty=t>>3 owns 8 rows (256-row tile).
// A tile k-major with 260-float row pitch: row-pairs adjacent -> packed A
// operands load directly as 64-bit words; STS transpose covers 32 banks.
#define XP_ 260
__global__ void __launch_bounds__(256, 2)
gemm1_kernel(const float* __restrict__ x, const float* __restrict__ W1,
             const float* __restrict__ as, const float* __restrict__ ad) {
    __shared__ float ws[INF_ * HC_];   // 32 KB, [k][c]
    __shared__ float xs[8 * XP_];      // 8.3 KB, [k_local][row(padded)]
    __shared__ float sa[HC_], sd[HC_];
    int t = threadIdx.x;
    int tx = t & 7, ty = t >> 3;
    int row0 = blockIdx.x * 256;

    if (t < HC_) { sa[t] = as[t]; sd[t] = ad[t]; }
    for (int i = t; i < INF_ * HC_ / 4; i += 256)
        ((float4*)ws)[i] = ((const float4*)W1)[i];

    ull acc[4][8];                     // [row-pair][col]
#pragma unroll
    for (int a = 0; a < 4; a++)
#pragma unroll
        for (int b = 0; b < 8; b++) acc[a][b] = 0ull;

    for (int c = 0; c < 16; c++) {     // 16 chunks of 8 k
        __syncthreads();
#pragma unroll
        for (int rep = 0; rep < 2; rep++) {
            int idx = t + rep * 256;   // 512 float4 loads per chunk
            int r = idx >> 1, q = idx & 1;
            int gr = row0 + r;
            float4 v = (gr < NN_) ? ((const float4*)x)[gr * 32 + c * 2 + q]
                                  : make_float4(0.f, 0.f, 0.f, 0.f);
            xs[(4 * q + 0) * XP_ + r] = v.x;   // transpose into [k][row]
            xs[(4 * q + 1) * XP_ + r] = v.y;
            xs[(4 * q + 2) * XP_ + r] = v.z;
            xs[(4 * q + 3) * XP_ + r] = v.w;
        }
        __syncthreads();
#pragma unroll
        for (int k = 0; k < 8; k++) {
            const ull* ap = (const ull*)&xs[k * XP_ + ty * 8];   // 4 row-pairs
            ull a0 = ap[0], a1 = ap[1], a2 = ap[2], a3 = ap[3];
            const float* wr = &ws[(c * 8 + k) * HC_ + tx * 8];
            float4 b0 = *(const float4*)&wr[0];
            float4 b1 = *(const float4*)&wr[4];
            ull p0 = pk2(b0.x, b0.x), p1 = pk2(b0.y, b0.y);
            ull p2 = pk2(b0.z, b0.z), p3 = pk2(b0.w, b0.w);
            ull p4 = pk2(b1.x, b1.x), p5 = pk2(b1.y, b1.y);
            ull p6 = pk2(b1.z, b1.z), p7 = pk2(b1.w, b1.w);
            ull av[4] = {a0, a1, a2, a3};
#pragma unroll
            for (int p = 0; p < 4; p++) {
                ull a = av[p];
                acc[p][0] = f2fma(a, p0, acc[p][0]);
                acc[p][1] = f2fma(a, p1, acc[p][1]);
                acc[p][2] = f2fma(a, p2, acc[p][2]);
                acc[p][3] = f2fma(a, p3, acc[p][3]);
                acc[p][4] = f2fma(a, p4, acc[p][4]);
                acc[p][5] = f2fma(a, p5, acc[p][5]);
                acc[p][6] = f2fma(a, p6, acc[p][6]);
                acc[p][7] = f2fma(a, p7, acc[p][7]);
            }
        }
    }
    // epilogue: unpack row-pairs, store + fused scores
#pragma unroll
    for (int p = 0; p < 4; p++) {
        float lo[8], hi[8];
#pragma unroll
        for (int cc = 0; cc < 8; cc++) up2(acc[p][cc], lo[cc], hi[cc]);
#pragma unroll
        for (int half = 0; half < 2; half++) {
            const float* v = half ? hi : lo;
            int n = row0 + ty * 8 + 2 * p + half;
            float pas = 0.f, pad = 0.f;
#pragma unroll
            for (int cc = 0; cc < 8; cc++) {
                pas = fmaf(v[cc], sa[tx * 8 + cc], pas);
                pad = fmaf(v[cc], sd[tx * 8 + cc], pad);
            }
            pas += __shfl_xor_sync(0xffffffffu, pas, 1);
            pas += __shfl_xor_sync(0xffffffffu, pas, 2);
            pad += __shfl_xor_sync(0xffffffffu, pad, 1);
            pad += __shfl_xor_sync(0xffffffffu, pad, 2);
            if (n < NN_) {
                *(float4*)&g_xl1[n * HC_ + tx * 8] =
                    make_float4(v[0], v[1], v[2], v[3]);
                *(float4*)&g_xl1[n * HC_ + tx * 8 + 4] =
                    make_float4(v[4], v[5], v[6], v[7]);
                if (tx == 0 || tx == 4) {        // tx<4: head0, tx>=4: head1
                    int h = tx >> 2;
                    g_as1[n * 2 + h] = pas;
                    g_ad1[n * 2 + h] = pad;
                }
            }
        }
    }
}

// ---------------- GEMM2 + scores2 fused (unchanged from passing R8) --------
__global__ void __launch_bounds__(256, 1)
gemm2_kernel(const float* __restrict__ W2,
             const float* __restrict__ as, const float* __restrict__ ad) {
    __shared__ float ws[HC_ * OC_];    //  8 KB, [k][c]
    __shared__ float xs[HC_ * 128];    // 32 KB, [k][row]
    __shared__ float sa[OC_], sd[OC_];
    int t = threadIdx.x;
    int tx = t & 3, ty = t >> 2;
    int row0 = blockIdx.x * 128;

    if (t < OC_) { sa[t] = as[t]; sd[t] = ad[t]; }
    for (int i = t; i < HC_ * OC_ / 4; i += 256)
        ((float4*)ws)[i] = ((const float4*)W2)[i];
    for (int idx = t; idx < 128 * 16; idx += 256) {
        int r = idx >> 4, q = idx & 15;
        int gr = row0 + r;
        float4 v = (gr < NN_) ? ((const float4*)g_h1)[gr * 16 + q]
                              : make_float4(0.f, 0.f, 0.f, 0.f);
        xs[(4 * q + 0) * 128 + r] = v.x;
        xs[(4 * q + 1) * 128 + r] = v.y;
        xs[(4 * q + 2) * 128 + r] = v.z;
        xs[(4 * q + 3) * 128 + r] = v.w;
    }
    __syncthreads();

    float acc[2][8];
#pragma unroll
    for (int a = 0; a < 2; a++)
#pragma unroll
        for (int b = 0; b < 8; b++) acc[a][b] = 0.f;

#pragma unroll 8
    for (int k = 0; k < HC_; k++) {
        float2 a2 = *(const float2*)&xs[k * 128 + ty * 2];
        const float* wr = &ws[k * OC_ + tx * 8];
        float4 b0 = *(const float4*)&wr[0];
        float4 b1 = *(const float4*)&wr[4];
        float av[2] = {a2.x, a2.y};
#pragma unroll
        for (int nn = 0; nn < 2; nn++) {
            float a = av[nn];
            acc[nn][0] = fmaf(a, b0.x, acc[nn][0]);
            acc[nn][1] = fmaf(a, b0.y, acc[nn][1]);
            acc[nn][2] = fmaf(a, b0.z, acc[nn][2]);
            acc[nn][3] = fmaf(a, b0.w, acc[nn][3]);
            acc[nn][4] = fmaf(a, b1.x, acc[nn][4]);
            acc[nn][5] = fmaf(a, b1.y, acc[nn][5]);
            acc[nn][6] = fmaf(a, b1.z, acc[nn][6]);
            acc[nn][7] = fmaf(a, b1.w, acc[nn][7]);
        }
    }
#pragma unroll
    for (int nn = 0; nn < 2; nn++) {
        int n = row0 + ty * 2 + nn;
        float pas = 0.f, pad = 0.f;
#pragma unroll
        for (int cc = 0; cc < 8; cc++) {
            pas = fmaf(acc[nn][cc], sa[tx * 8 + cc], pas);
            pad = fmaf(acc[nn][cc], sd[tx * 8 + cc], pad);
        }
        pas += __shfl_xor_sync(0xffffffffu, pas, 1);
        pas += __shfl_xor_sync(0xffffffffu, pas, 2);
        pad += __shfl_xor_sync(0xffffffffu, pad, 1);
        pad += __shfl_xor_sync(0xffffffffu, pad, 2);
        if (n < NN_) {
            *(float4*)&g_xl2[n * OC_ + tx * 8] =
                make_float4(acc[nn][0], acc[nn][1], acc[nn][2], acc[nn][3]);
            *(float4*)&g_xl2[n * OC_ + tx * 8 + 4] =
                make_float4(acc[nn][4], acc[nn][5], acc[nn][6], acc[nn][7]);
            if (tx == 0) { g_as2[n] = pas; g_ad2[n] = pad; }
        }
    }
}

// ---------------- layer-1 aggregation (warp per dst node) ----------------
__global__ void agg1_kernel(const float* __restrict__ b1) {
    int g = blockIdx.x * blockDim.x + threadIdx.x;
    int n = g >> 5, lane = g & 31;
    if (n >= NN_) return;
    float ex0 = __expf(lrelu(g_as1[n * 2 + 0] + g_ad1[n * 2 + 0]));  // self loop
    float ex1 = __expf(lrelu(g_as1[n * 2 + 1] + g_ad1[n * 2 + 1]));
    float den0 = ex0, den1 = ex1;
    const float2* xl = (const float2*)g_xl1;
    float2 v = xl[n * 32 + lane];
    bool h0 = lane < 16;                 // lanes 0-15: head0 channels, 16-31: head1
    float exm = h0 ? ex0 : ex1;
    float ax = exm * v.x, ay = exm * v.y;
    int st = g_ptr[n], de = g_deg[n];
    for (int j = 0; j < de; j++) {
        int s = g_esrc[st + j];          // broadcast
        float2 f = g_eex1[st + j];       // broadcast
        den0 += f.x; den1 += f.y;
        float2 w = xl[s * 32 + lane];    // 256B row gather
        float fm = h0 ? f.x : f.y;
        ax = fmaf(fm, w.x, ax);
        ay = fmaf(fm, w.y, ay);
    }
    float den = h0 ? den0 : den1;
    float inv = 1.f / (den + 1e-16f);
    float bx = b1[lane * 2], by = b1[lane * 2 + 1];
    float2 o;
    o.x = fmaxf(fmaf(ax, inv, bx), 0.f);   // bias + ReLU fused
    o.y = fmaxf(fmaf(ay, inv, by), 0.f);
    ((float2*)g_h1)[n * 32 + lane] = o;
}

// ---------------- layer-2 edge exp + aggregation ----------------
__global__ void exp2_kernel() {
    int p = blockIdx.x * blockDim.x + threadIdx.x;
    if (p >= NE_) return;
    g_eex2[p] = __expf(lrelu(g_as2[g_esrc[p]] + g_ad2[g_edst[p]]));
}
__global__ void agg2_kernel(const float* __restrict__ b2, float* __restrict__ out) {
    int g = blockIdx.x * blockDim.x + threadIdx.x;
    int n = g >> 5, lane = g & 31;
    if (n >= NN_) return;
    float ex = __expf(lrelu(g_as2[n] + g_ad2[n]));   // self loop
    float den = ex;
    float acc = ex * g_xl2[n * OC_ + lane];
    int st = g_ptr[n], de = g_deg[n];
    for (int j = 0; j < de; j++) {
        int s = g_esrc[st + j];          // broadcast
        float f = g_eex2[st + j];        // broadcast
        den += f;
        acc = fmaf(f, g_xl2[s * OC_ + lane], acc);   // 128B row gather
    }
    out[n * OC_ + lane] = acc / (den + 1e-16f) + b2[lane];
}

// ---------------- launch ----------------
extern "C" void kernel_launch(void* const* d_in, const int* in_sizes, int n_in,
                              void* d_out, int out_size) {
    // size-keyed input remap with positional fallback
    const float* x = 0; const int* ei = 0;
    const float* W1 = 0; const float* W2 = 0;
    const float* a64[3] = {0, 0, 0}; int n64 = 0;
    const float* a32[3] = {0, 0, 0}; int n32 = 0;
    for (int i = 0; i < n_in; i++) {
        int sz = in_sizes[i];
        if      (sz == NN_ * INF_) x  = (const float*)d_in[i];
        else if (sz == 2 * NE_)    ei = (const int*)  d_in[i];
        else if (sz == INF_ * HC_) W1 = (const float*)d_in[i];
        else if (sz == HC_ * OC_)  W2 = (const float*)d_in[i];
        else if (sz == HC_) { if (n64 < 3) a64[n64++] = (const float*)d_in[i]; }
        else if (sz == OC_) { if (n32 < 3) a32[n32++] = (const float*)d_in[i]; }
    }
    if (!x)  x  = (const float*)d_in[0];
    if (!ei) ei = (const int*)  d_in[1];
    if (!W1) W1 = (const float*)d_in[2];
    if (!W2) W2 = (const float*)d_in[6];
    const float* as1 = a64[0] ? a64[0] : (const float*)d_in[3];
    const float* ad1 = a64[1] ? a64[1] : (const float*)d_in[4];
    const float* b1  = a64[2] ? a64[2] : (const float*)d_in[5];
    const float* as2 = a32[0] ? a32[0] : (const float*)d_in[7];
    const float* ad2 = a32[1] ? a32[1] : (const float*)d_in[8];
    const float* b2  = a32[2] ? a32[2] : (const float*)d_in[9];
    float* out = (float*)d_out;

    const int* srcp = ei;
    const int* dstp = ei + NE_;

    const int NB  = (NN_ + 255) / 256;         // node blocks
    const int EB  = (NE_ + 255) / 256;         // edge blocks
    const int G1  = (NN_ + 255) / 256;         // 391 gemm1 blocks (256 rows)
    const int G2  = (NN_ + 127) / 128;         // 782 gemm2 blocks (128 rows)
    const int WB  = (NN_ * 32 + 255) / 256;    // 12500 warp-per-node blocks

    prep_kernel<<<NB, 256>>>();
    hist_kernel<<<EB, 256>>>(dstp);
    ptr_kernel<<<NB, 256>>>();

    gemm1_kernel<<<G1, 256>>>(x, W1, as1, ad1);
    scatter_kernel<<<EB, 256>>>(srcp, dstp);
    agg1_kernel<<<WB, 256>>>(b1);

    gemm2_kernel<<<G2, 256>>>(W2, as2, ad2);
    exp2_kernel<<<EB, 256>>>();
    agg2_kernel<<<WB, 256>>>(b2, out);

    (void)n_in; (void)out_size;
}

// round 10
// speedup vs baseline: 1.5109x; 1.0535x over previous
#include <cuda_runtime.h>

#define NN_ 100000
#define NE_ 1600000
#define INF_ 128
#define HC_ 64
#define OC_ 32

// ---------------- scratch (static device globals; no allocation) ----------------
__device__ __align__(16) float  g_xl1[NN_ * HC_];   // x @ W1     (25.6 MB)
__device__ __align__(16) float  g_h1 [NN_ * HC_];   // relu(gat1) (25.6 MB)
__device__ __align__(16) float  g_xl2[NN_ * OC_];   // h @ W2     (12.8 MB)
__device__ float  g_as1[NN_ * 2];                   // layer1 per-node scores
__device__ float  g_ad1[NN_ * 2];
__device__ float  g_as2[NN_];
__device__ float  g_ad2[NN_];
__device__ int    g_deg[NN_];
__device__ int    g_ptr[NN_];
__device__ int    g_cur[NN_];
__device__ int    g_total;
__device__ int    g_esrc[NE_];
__device__ int    g_edst[NE_];
__device__ __align__(8) float2 g_eex1[NE_];         // exp(leaky(e)) layer1, 2 heads
__device__ float  g_eex2[NE_];

__device__ __forceinline__ float lrelu(float x) { return x > 0.f ? x : 0.2f * x; }

typedef unsigned long long ull;
__device__ __forceinline__ ull pk2(float x, float y) {
    ull r; asm("mov.b64 %0,{%1,%2};" : "=l"(r) : "f"(x), "f"(y)); return r;
}
__device__ __forceinline__ void up2(ull v, float& x, float& y) {
    asm("mov.b64 {%0,%1},%2;" : "=f"(x), "=f"(y) : "l"(v));
}
// packed fp32x2 FMA (FFMA2): d.lo=fma(a.lo,b.lo,c.lo), d.hi likewise
__device__ __forceinline__ ull f2fma(ull a, ull b, ull c) {
    ull d; asm("fma.rn.f32x2 %0,%1,%2,%3;" : "=l"(d) : "l"(a), "l"(b), "l"(c)); return d;
}

// ---------------- CSR build (no scans: bins in arbitrary order) ----------------
__global__ void prep_kernel() {
    int i = blockIdx.x * blockDim.x + threadIdx.x;
    if (i < NN_) g_deg[i] = 0;
    if (i == 0) g_total = 0;
}
__global__ void hist_kernel(const int* __restrict__ dst) {
    int i = blockIdx.x * blockDim.x + threadIdx.x;
    if (i < NE_) atomicAdd(&g_deg[dst[i]], 1);
}
__global__ void ptr_kernel() {
    int i = blockIdx.x * blockDim.x + threadIdx.x;
    if (i < NN_) {
        int p = atomicAdd(&g_total, g_deg[i]);   // bin offset (order irrelevant)
        g_ptr[i] = p;
        g_cur[i] = p;                            // scatter cursor starts at bin base
    }
}
// scatter edges into bins; precompute per-edge exp(leaky(e)) for layer 1
__global__ void scatter_kernel(const int* __restrict__ src,
                               const int* __restrict__ dst) {
    int i = blockIdx.x * blockDim.x + threadIdx.x;
    if (i >= NE_) return;
    int s = src[i], d = dst[i];
    int p = atomicAdd(&g_cur[d], 1);             // single atomic, no ptr load
    if (p < 0 || p >= NE_) return;               // defensive: never corrupt memory
    g_esrc[p] = s;
    g_edst[p] = d;
    float e0 = g_as1[s * 2 + 0] + g_ad1[d * 2 + 0];
    float e1 = g_as1[s * 2 + 1] + g_ad1[d * 2 + 1];
    g_eex1[p] = make_float2(__expf(lrelu(e0)), __expf(lrelu(e1)));
}

// ---------------- GEMM1 + scores1 fused (FFMA2, 8x8, reg prefetch) ----------
// xl1[N][64] = x[N][128] @ W1[128][64]; scores fused in epilogue.
// 256 threads: tx=t&7 owns 8 cols, ty=t>>3 owns 8 rows (256-row tile).
// Chunk c+1 prefetched into registers while chunk c computes (hides LDG).
#define XP_ 260
__global__ void __launch_bounds__(256, 2)
gemm1_kernel(const float* __restrict__ x, const float* __restrict__ W1,
             const float* __restrict__ as, const float* __restrict__ ad) {
    __shared__ float ws[INF_ * HC_];   // 32 KB, [k][c]
    __shared__ float xs[8 * XP_];      // 8.3 KB, [k_local][row(padded)]
    __shared__ float sa[HC_], sd[HC_];
    int t = threadIdx.x;
    int tx = t & 7, ty = t >> 3;
    int row0 = blockIdx.x * 256;

    if (t < HC_) { sa[t] = as[t]; sd[t] = ad[t]; }
    for (int i = t; i < INF_ * HC_ / 4; i += 256)
        ((float4*)ws)[i] = ((const float4*)W1)[i];

    // per-thread A-load coordinates (2 float4 per chunk)
    int r0 = t >> 1,          q0 = t & 1;
    int r1 = (t + 256) >> 1,  q1 = (t + 256) & 1;
    int gr0 = row0 + r0, gr1 = row0 + r1;
    const float4 z4 = make_float4(0.f, 0.f, 0.f, 0.f);

    float4 pre0 = (gr0 < NN_) ? ((const float4*)x)[gr0 * 32 + q0] : z4;
    float4 pre1 = (gr1 < NN_) ? ((const float4*)x)[gr1 * 32 + q1] : z4;

    ull acc[4][8];                     // [row-pair][col]
#pragma unroll
    for (int a = 0; a < 4; a++)
#pragma unroll
        for (int b = 0; b < 8; b++) acc[a][b] = 0ull;

    for (int c = 0; c < 16; c++) {     // 16 chunks of 8 k
        __syncthreads();               // previous compute done
        xs[(4 * q0 + 0) * XP_ + r0] = pre0.x;   // transpose into [k][row]
        xs[(4 * q0 + 1) * XP_ + r0] = pre0.y;
        xs[(4 * q0 + 2) * XP_ + r0] = pre0.z;
        xs[(4 * q0 + 3) * XP_ + r0] = pre0.w;
        xs[(4 * q1 + 0) * XP_ + r1] = pre1.x;
        xs[(4 * q1 + 1) * XP_ + r1] = pre1.y;
        xs[(4 * q1 + 2) * XP_ + r1] = pre1.z;
        xs[(4 * q1 + 3) * XP_ + r1] = pre1.w;
        __syncthreads();
        if (c < 15) {                  // prefetch next chunk under compute
            pre0 = (gr0 < NN_) ? ((const float4*)x)[gr0 * 32 + (c + 1) * 2 + q0] : z4;
            pre1 = (gr1 < NN_) ? ((const float4*)x)[gr1 * 32 + (c + 1) * 2 + q1] : z4;
        }
#pragma unroll
        for (int k = 0; k < 8; k++) {
            const ull* ap = (const ull*)&xs[k * XP_ + ty * 8];   // 4 row-pairs
            ull a0 = ap[0], a1 = ap[1], a2 = ap[2], a3 = ap[3];
            const float* wr = &ws[(c * 8 + k) * HC_ + tx * 8];
            float4 b0 = *(const float4*)&wr[0];
            float4 b1 = *(const float4*)&wr[4];
            ull p0 = pk2(b0.x, b0.x), p1 = pk2(b0.y, b0.y);
            ull p2 = pk2(b0.z, b0.z), p3 = pk2(b0.w, b0.w);
            ull p4 = pk2(b1.x, b1.x), p5 = pk2(b1.y, b1.y);
            ull p6 = pk2(b1.z, b1.z), p7 = pk2(b1.w, b1.w);
            ull av[4] = {a0, a1, a2, a3};
#pragma unroll
            for (int p = 0; p < 4; p++) {
                ull a = av[p];
                acc[p][0] = f2fma(a, p0, acc[p][0]);
                acc[p][1] = f2fma(a, p1, acc[p][1]);
                acc[p][2] = f2fma(a, p2, acc[p][2]);
                acc[p][3] = f2fma(a, p3, acc[p][3]);
                acc[p][4] = f2fma(a, p4, acc[p][4]);
                acc[p][5] = f2fma(a, p5, acc[p][5]);
                acc[p][6] = f2fma(a, p6, acc[p][6]);
                acc[p][7] = f2fma(a, p7, acc[p][7]);
            }
        }
    }
    // epilogue: unpack row-pairs, store + fused scores
#pragma unroll
    for (int p = 0; p < 4; p++) {
        float lo[8], hi[8];
#pragma unroll
        for (int cc = 0; cc < 8; cc++) up2(acc[p][cc], lo[cc], hi[cc]);
#pragma unroll
        for (int half = 0; half < 2; half++) {
            const float* v = half ? hi : lo;
            int n = row0 + ty * 8 + 2 * p + half;
            float pas = 0.f, pad = 0.f;
#pragma unroll
            for (int cc = 0; cc < 8; cc++) {
                pas = fmaf(v[cc], sa[tx * 8 + cc], pas);
                pad = fmaf(v[cc], sd[tx * 8 + cc], pad);
            }
            pas += __shfl_xor_sync(0xffffffffu, pas, 1);
            pas += __shfl_xor_sync(0xffffffffu, pas, 2);
            pad += __shfl_xor_sync(0xffffffffu, pad, 1);
            pad += __shfl_xor_sync(0xffffffffu, pad, 2);
            if (n < NN_) {
                *(float4*)&g_xl1[n * HC_ + tx * 8] =
                    make_float4(v[0], v[1], v[2], v[3]);
                *(float4*)&g_xl1[n * HC_ + tx * 8 + 4] =
                    make_float4(v[4], v[5], v[6], v[7]);
                if (tx == 0 || tx == 4) {        // tx<4: head0, tx>=4: head1
                    int h = tx >> 2;
                    g_as1[n * 2 + h] = pas;
                    g_ad1[n * 2 + h] = pad;
                }
            }
        }
    }
}

// ---------------- GEMM2 + scores2 fused (FFMA2, 8x8, BM=512) ----------------
// xl2[N][32] = h1[N][64] @ W2[64][32]. tx=t&3 owns 8 cols, ty=t>>2 owns 8 rows.
#define XP2_ 516
__global__ void __launch_bounds__(256, 2)
gemm2_kernel(const float* __restrict__ W2,
             const float* __restrict__ as, const float* __restrict__ ad) {
    __shared__ float ws[HC_ * OC_];    //  8 KB, [k][c]
    __shared__ float xs[8 * XP2_];     // 16.5 KB, [k_local][row(padded)]
    __shared__ float sa[OC_], sd[OC_];
    int t = threadIdx.x;
    int tx = t & 3, ty = t >> 2;
    int row0 = blockIdx.x * 512;

    if (t < OC_) { sa[t] = as[t]; sd[t] = ad[t]; }
    for (int i = t; i < HC_ * OC_ / 4; i += 256)
        ((float4*)ws)[i] = ((const float4*)W2)[i];

    // per-thread A-load coordinates (4 float4 per chunk: 512 rows x 8k)
    int rr[4], qq[4], gg[4];
#pragma unroll
    for (int rep = 0; rep < 4; rep++) {
        int idx = t + rep * 256;
        rr[rep] = idx >> 1; qq[rep] = idx & 1; gg[rep] = row0 + rr[rep];
    }
    const float4 z4 = make_float4(0.f, 0.f, 0.f, 0.f);
    float4 pre[4];
#pragma unroll
    for (int rep = 0; rep < 4; rep++)
        pre[rep] = (gg[rep] < NN_) ? ((const float4*)g_h1)[gg[rep] * 16 + qq[rep]] : z4;

    ull acc[4][8];                     // [row-pair][col]
#pragma unroll
    for (int a = 0; a < 4; a++)
#pragma unroll
        for (int b = 0; b < 8; b++) acc[a][b] = 0ull;

    for (int c = 0; c < 8; c++) {      // 8 chunks of 8 k
        __syncthreads();
#pragma unroll
        for (int rep = 0; rep < 4; rep++) {
            int r = rr[rep], q = qq[rep];
            xs[(4 * q + 0) * XP2_ + r] = pre[rep].x;
            xs[(4 * q + 1) * XP2_ + r] = pre[rep].y;
            xs[(4 * q + 2) * XP2_ + r] = pre[rep].z;
            xs[(4 * q + 3) * XP2_ + r] = pre[rep].w;
        }
        __syncthreads();
        if (c < 7) {
#pragma unroll
            for (int rep = 0; rep < 4; rep++)
                pre[rep] = (gg[rep] < NN_)
                    ? ((const float4*)g_h1)[gg[rep] * 16 + (c + 1) * 2 + qq[rep]] : z4;
        }
#pragma unroll
        for (int k = 0; k < 8; k++) {
            const ull* ap = (const ull*)&xs[k * XP2_ + ty * 8];
            ull a0 = ap[0], a1 = ap[1], a2 = ap[2], a3 = ap[3];
            const float* wr = &ws[(c * 8 + k) * OC_ + tx * 8];
            float4 b0 = *(const float4*)&wr[0];
            float4 b1 = *(const float4*)&wr[4];
            ull p0 = pk2(b0.x, b0.x), p1 = pk2(b0.y, b0.y);
            ull p2 = pk2(b0.z, b0.z), p3 = pk2(b0.w, b0.w);
            ull p4 = pk2(b1.x, b1.x), p5 = pk2(b1.y, b1.y);
            ull p6 = pk2(b1.z, b1.z), p7 = pk2(b1.w, b1.w);
            ull av[4] = {a0, a1, a2, a3};
#pragma unroll
            for (int p = 0; p < 4; p++) {
                ull a = av[p];
                acc[p][0] = f2fma(a, p0, acc[p][0]);
                acc[p][1] = f2fma(a, p1, acc[p][1]);
                acc[p][2] = f2fma(a, p2, acc[p][2]);
                acc[p][3] = f2fma(a, p3, acc[p][3]);
                acc[p][4] = f2fma(a, p4, acc[p][4]);
                acc[p][5] = f2fma(a, p5, acc[p][5]);
                acc[p][6] = f2fma(a, p6, acc[p][6]);
                acc[p][7] = f2fma(a, p7, acc[p][7]);
            }
        }
    }
    // epilogue: unpack + store + fused scores (tx groups of 4 cover 32 cols)
#pragma unroll
    for (int p = 0; p < 4; p++) {
        float lo[8], hi[8];
#pragma unroll
        for (int cc = 0; cc < 8; cc++) up2(acc[p][cc], lo[cc], hi[cc]);
#pragma unroll
        for (int half = 0; half < 2; half++) {
            const float* v = half ? hi : lo;
            int n = row0 + ty * 8 + 2 * p + half;
            float pas = 0.f, pad = 0.f;
#pragma unroll
            for (int cc = 0; cc < 8; cc++) {
                pas = fmaf(v[cc], sa[tx * 8 + cc], pas);
                pad = fmaf(v[cc], sd[tx * 8 + cc], pad);
            }
            pas += __shfl_xor_sync(0xffffffffu, pas, 1);
            pas += __shfl_xor_sync(0xffffffffu, pas, 2);
            pad += __shfl_xor_sync(0xffffffffu, pad, 1);
            pad += __shfl_xor_sync(0xffffffffu, pad, 2);
            if (n < NN_) {
                *(float4*)&g_xl2[n * OC_ + tx * 8] =
                    make_float4(v[0], v[1], v[2], v[3]);
                *(float4*)&g_xl2[n * OC_ + tx * 8 + 4] =
                    make_float4(v[4], v[5], v[6], v[7]);
                if (tx == 0) { g_as2[n] = pas; g_ad2[n] = pad; }
            }
        }
    }
}

// ---------------- layer-1 aggregation (warp per dst node) ----------------
__global__ void agg1_kernel(const float* __restrict__ b1) {
    int g = blockIdx.x * blockDim.x + threadIdx.x;
    int n = g >> 5, lane = g & 31;
    if (n >= NN_) return;
    float ex0 = __expf(lrelu(g_as1[n * 2 + 0] + g_ad1[n * 2 + 0]));  // self loop
    float ex1 = __expf(lrelu(g_as1[n * 2 + 1] + g_ad1[n * 2 + 1]));
    float den0 = ex0, den1 = ex1;
    const float2* xl = (const float2*)g_xl1;
    float2 v = xl[n * 32 + lane];
    bool h0 = lane < 16;                 // lanes 0-15: head0 channels, 16-31: head1
    float exm = h0 ? ex0 : ex1;
    float ax = exm * v.x, ay = exm * v.y;
    int st = g_ptr[n], de = g_deg[n];
    for (int j = 0; j < de; j++) {
        int s = g_esrc[st + j];          // broadcast
        float2 f = g_eex1[st + j];       // broadcast
        den0 += f.x; den1 += f.y;
        float2 w = xl[s * 32 + lane];    // 256B row gather
        float fm = h0 ? f.x : f.y;
        ax = fmaf(fm, w.x, ax);
        ay = fmaf(fm, w.y, ay);
    }
    float den = h0 ? den0 : den1;
    float inv = 1.f / (den + 1e-16f);
    float bx = b1[lane * 2], by = b1[lane * 2 + 1];
    float2 o;
    o.x = fmaxf(fmaf(ax, inv, bx), 0.f);   // bias + ReLU fused
    o.y = fmaxf(fmaf(ay, inv, by), 0.f);
    ((float2*)g_h1)[n * 32 + lane] = o;
}

// ---------------- layer-2 edge exp + aggregation ----------------
__global__ void exp2_kernel() {
    int p = blockIdx.x * blockDim.x + threadIdx.x;
    if (p >= NE_) return;
    g_eex2[p] = __expf(lrelu(g_as2[g_esrc[p]] + g_ad2[g_edst[p]]));
}
__global__ void agg2_kernel(const float* __restrict__ b2, float* __restrict__ out) {
    int g = blockIdx.x * blockDim.x + threadIdx.x;
    int n = g >> 5, lane = g & 31;
    if (n >= NN_) return;
    float ex = __expf(lrelu(g_as2[n] + g_ad2[n]));   // self loop
    float den = ex;
    float acc = ex * g_xl2[n * OC_ + lane];
    int st = g_ptr[n], de = g_deg[n];
    for (int j = 0; j < de; j++) {
        int s = g_esrc[st + j];          // broadcast
        float f = g_eex2[st + j];        // broadcast
        den += f;
        acc = fmaf(f, g_xl2[s * OC_ + lane], acc);   // 128B row gather
    }
    out[n * OC_ + lane] = acc / (den + 1e-16f) + b2[lane];
}

// ---------------- launch ----------------
extern "C" void kernel_launch(void* const* d_in, const int* in_sizes, int n_in,
                              void* d_out, int out_size) {
    // size-keyed input remap with positional fallback
    const float* x = 0; const int* ei = 0;
    const float* W1 = 0; const float* W2 = 0;
    const float* a64[3] = {0, 0, 0}; int n64 = 0;
    const float* a32[3] = {0, 0, 0}; int n32 = 0;
    for (int i = 0; i < n_in; i++) {
        int sz = in_sizes[i];
        if      (sz == NN_ * INF_) x  = (const float*)d_in[i];
        else if (sz == 2 * NE_)    ei = (const int*)  d_in[i];
        else if (sz == INF_ * HC_) W1 = (const float*)d_in[i];
        else if (sz == HC_ * OC_)  W2 = (const float*)d_in[i];
        else if (sz == HC_) { if (n64 < 3) a64[n64++] = (const float*)d_in[i]; }
        else if (sz == OC_) { if (n32 < 3) a32[n32++] = (const float*)d_in[i]; }
    }
    if (!x)  x  = (const float*)d_in[0];
    if (!ei) ei = (const int*)  d_in[1];
    if (!W1) W1 = (const float*)d_in[2];
    if (!W2) W2 = (const float*)d_in[6];
    const float* as1 = a64[0] ? a64[0] : (const float*)d_in[3];
    const float* ad1 = a64[1] ? a64[1] : (const float*)d_in[4];
    const float* b1  = a64[2] ? a64[2] : (const float*)d_in[5];
    const float* as2 = a32[0] ? a32[0] : (const float*)d_in[7];
    const float* ad2 = a32[1] ? a32[1] : (const float*)d_in[8];
    const float* b2  = a32[2] ? a32[2] : (const float*)d_in[9];
    float* out = (float*)d_out;

    const int* srcp = ei;
    const int* dstp = ei + NE_;

    const int NB  = (NN_ + 255) / 256;         // node blocks
    const int EB  = (NE_ + 255) / 256;         // edge blocks
    const int G1  = (NN_ + 255) / 256;         // 391 gemm1 blocks (256 rows)
    const int G2  = (NN_ + 511) / 512;         // 196 gemm2 blocks (512 rows)
    const int WB  = (NN_ * 32 + 255) / 256;    // 12500 warp-per-node blocks

    prep_kernel<<<NB, 256>>>();
    hist_kernel<<<EB, 256>>>(dstp);
    ptr_kernel<<<NB, 256>>>();

    gemm1_kernel<<<G1, 256>>>(x, W1, as1, ad1);
    scatter_kernel<<<EB, 256>>>(srcp, dstp);
    agg1_kernel<<<WB, 256>>>(b1);

    gemm2_kernel<<<G2, 256>>>(W2, as2, ad2);
    exp2_kernel<<<EB, 256>>>();
    agg2_kernel<<<WB, 256>>>(b2, out);

    (void)n_in; (void)out_size;
}

// round 11
// speedup vs baseline: 1.5139x; 1.0020x over previous
#include <cuda_runtime.h>

#define NN_ 100000
#define NE_ 1600000
#define INF_ 128
#define HC_ 64
#define OC_ 32

// ---------------- scratch (static device globals; no allocation) ----------------
__device__ __align__(16) float  g_xl1[NN_ * HC_];   // x @ W1     (25.6 MB)
__device__ __align__(16) float  g_h1 [NN_ * HC_];   // relu(gat1) (25.6 MB)
__device__ __align__(16) float  g_xl2[NN_ * OC_];   // h @ W2     (12.8 MB)
__device__ float  g_as1[NN_ * 2];                   // layer1 per-node scores
__device__ float  g_ad1[NN_ * 2];
__device__ float  g_as2[NN_];
__device__ float  g_ad2[NN_];
__device__ int    g_deg[NN_];
__device__ int    g_ptr[NN_];
__device__ int    g_cur[NN_];
__device__ int    g_total;
__device__ __align__(16) float4 g_erec[NE_];        // {src, ex0, ex1, -} (25.6 MB)

__device__ __forceinline__ float lrelu(float x) { return x > 0.f ? x : 0.2f * x; }

typedef unsigned long long ull;
__device__ __forceinline__ ull pk2(float x, float y) {
    ull r; asm("mov.b64 %0,{%1,%2};" : "=l"(r) : "f"(x), "f"(y)); return r;
}
__device__ __forceinline__ void up2(ull v, float& x, float& y) {
    asm("mov.b64 {%0,%1},%2;" : "=f"(x), "=f"(y) : "l"(v));
}
// packed fp32x2 FMA (FFMA2): d.lo=fma(a.lo,b.lo,c.lo), d.hi likewise
__device__ __forceinline__ ull f2fma(ull a, ull b, ull c) {
    ull d; asm("fma.rn.f32x2 %0,%1,%2,%3;" : "=l"(d) : "l"(a), "l"(b), "l"(c)); return d;
}

// ---------------- CSR build (no scans: bins in arbitrary order) ----------------
__global__ void prep_kernel() {
    int i = blockIdx.x * blockDim.x + threadIdx.x;
    if (i < NN_) g_deg[i] = 0;
    if (i == 0) g_total = 0;
}
__global__ void hist_kernel(const int* __restrict__ dst) {
    int i = blockIdx.x * blockDim.x + threadIdx.x;
    if (i < NE_) atomicAdd(&g_deg[dst[i]], 1);
}
__global__ void ptr_kernel() {
    int i = blockIdx.x * blockDim.x + threadIdx.x;
    if (i < NN_) {
        int p = atomicAdd(&g_total, g_deg[i]);   // bin offset (order irrelevant)
        g_ptr[i] = p;
        g_cur[i] = p;                            // scatter cursor starts at bin base
    }
}
// scatter edges into bins; one packed 16B record per edge (1 L2 sector, not 3)
__global__ void scatter_kernel(const int* __restrict__ src,
                               const int* __restrict__ dst) {
    int i = blockIdx.x * blockDim.x + threadIdx.x;
    if (i >= NE_) return;
    int s = src[i], d = dst[i];
    int p = atomicAdd(&g_cur[d], 1);
    if (p < 0 || p >= NE_) return;               // defensive: never corrupt memory
    float e0 = g_as1[s * 2 + 0] + g_ad1[d * 2 + 0];
    float e1 = g_as1[s * 2 + 1] + g_ad1[d * 2 + 1];
    g_erec[p] = make_float4(__int_as_float(s),
                            __expf(lrelu(e0)), __expf(lrelu(e1)), 0.f);
}

// ---------------- GEMM1 + scores1 fused (FFMA2, 8x8, reg prefetch) ----------
#define XP_ 260
__global__ void __launch_bounds__(256, 2)
gemm1_kernel(const float* __restrict__ x, const float* __restrict__ W1,
             const float* __restrict__ as, const float* __restrict__ ad) {
    __shared__ float ws[INF_ * HC_];   // 32 KB, [k][c]
    __shared__ float xs[8 * XP_];      // 8.3 KB, [k_local][row(padded)]
    __shared__ float sa[HC_], sd[HC_];
    int t = threadIdx.x;
    int tx = t & 7, ty = t >> 3;
    int row0 = blockIdx.x * 256;

    if (t < HC_) { sa[t] = as[t]; sd[t] = ad[t]; }
    for (int i = t; i < INF_ * HC_ / 4; i += 256)
        ((float4*)ws)[i] = ((const float4*)W1)[i];

    int r0 = t >> 1,          q0 = t & 1;
    int r1 = (t + 256) >> 1,  q1 = (t + 256) & 1;
    int gr0 = row0 + r0, gr1 = row0 + r1;
    const float4 z4 = make_float4(0.f, 0.f, 0.f, 0.f);

    float4 pre0 = (gr0 < NN_) ? ((const float4*)x)[gr0 * 32 + q0] : z4;
    float4 pre1 = (gr1 < NN_) ? ((const float4*)x)[gr1 * 32 + q1] : z4;

    ull acc[4][8];                     // [row-pair][col]
#pragma unroll
    for (int a = 0; a < 4; a++)
#pragma unroll
        for (int b = 0; b < 8; b++) acc[a][b] = 0ull;

    for (int c = 0; c < 16; c++) {     // 16 chunks of 8 k
        __syncthreads();
        xs[(4 * q0 + 0) * XP_ + r0] = pre0.x;
        xs[(4 * q0 + 1) * XP_ + r0] = pre0.y;
        xs[(4 * q0 + 2) * XP_ + r0] = pre0.z;
        xs[(4 * q0 + 3) * XP_ + r0] = pre0.w;
        xs[(4 * q1 + 0) * XP_ + r1] = pre1.x;
        xs[(4 * q1 + 1) * XP_ + r1] = pre1.y;
        xs[(4 * q1 + 2) * XP_ + r1] = pre1.z;
        xs[(4 * q1 + 3) * XP_ + r1] = pre1.w;
        __syncthreads();
        if (c < 15) {
            pre0 = (gr0 < NN_) ? ((const float4*)x)[gr0 * 32 + (c + 1) * 2 + q0] : z4;
            pre1 = (gr1 < NN_) ? ((const float4*)x)[gr1 * 32 + (c + 1) * 2 + q1] : z4;
        }
#pragma unroll
        for (int k = 0; k < 8; k++) {
            const ull* ap = (const ull*)&xs[k * XP_ + ty * 8];
            ull a0 = ap[0], a1 = ap[1], a2 = ap[2], a3 = ap[3];
            const float* wr = &ws[(c * 8 + k) * HC_ + tx * 8];
            float4 b0 = *(const float4*)&wr[0];
            float4 b1 = *(const float4*)&wr[4];
            ull p0 = pk2(b0.x, b0.x), p1 = pk2(b0.y, b0.y);
            ull p2 = pk2(b0.z, b0.z), p3 = pk2(b0.w, b0.w);
            ull p4 = pk2(b1.x, b1.x), p5 = pk2(b1.y, b1.y);
            ull p6 = pk2(b1.z, b1.z), p7 = pk2(b1.w, b1.w);
            ull av[4] = {a0, a1, a2, a3};
#pragma unroll
            for (int p = 0; p < 4; p++) {
                ull a = av[p];
                acc[p][0] = f2fma(a, p0, acc[p][0]);
                acc[p][1] = f2fma(a, p1, acc[p][1]);
                acc[p][2] = f2fma(a, p2, acc[p][2]);
                acc[p][3] = f2fma(a, p3, acc[p][3]);
                acc[p][4] = f2fma(a, p4, acc[p][4]);
                acc[p][5] = f2fma(a, p5, acc[p][5]);
                acc[p][6] = f2fma(a, p6, acc[p][6]);
                acc[p][7] = f2fma(a, p7, acc[p][7]);
            }
        }
    }
#pragma unroll
    for (int p = 0; p < 4; p++) {
        float lo[8], hi[8];
#pragma unroll
        for (int cc = 0; cc < 8; cc++) up2(acc[p][cc], lo[cc], hi[cc]);
#pragma unroll
        for (int half = 0; half < 2; half++) {
            const float* v = half ? hi : lo;
            int n = row0 + ty * 8 + 2 * p + half;
            float pas = 0.f, pad = 0.f;
#pragma unroll
            for (int cc = 0; cc < 8; cc++) {
                pas = fmaf(v[cc], sa[tx * 8 + cc], pas);
                pad = fmaf(v[cc], sd[tx * 8 + cc], pad);
            }
            pas += __shfl_xor_sync(0xffffffffu, pas, 1);
            pas += __shfl_xor_sync(0xffffffffu, pas, 2);
            pad += __shfl_xor_sync(0xffffffffu, pad, 1);
            pad += __shfl_xor_sync(0xffffffffu, pad, 2);
            if (n < NN_) {
                *(float4*)&g_xl1[n * HC_ + tx * 8] =
                    make_float4(v[0], v[1], v[2], v[3]);
                *(float4*)&g_xl1[n * HC_ + tx * 8 + 4] =
                    make_float4(v[4], v[5], v[6], v[7]);
                if (tx == 0 || tx == 4) {
                    int h = tx >> 2;
                    g_as1[n * 2 + h] = pas;
                    g_ad1[n * 2 + h] = pad;
                }
            }
        }
    }
}

// ---------------- GEMM2 + scores2 fused (FFMA2, 8x8, BM=512) ----------------
#define XP2_ 516
__global__ void __launch_bounds__(256, 2)
gemm2_kernel(const float* __restrict__ W2,
             const float* __restrict__ as, const float* __restrict__ ad) {
    __shared__ float ws[HC_ * OC_];    //  8 KB, [k][c]
    __shared__ float xs[8 * XP2_];     // 16.5 KB, [k_local][row(padded)]
    __shared__ float sa[OC_], sd[OC_];
    int t = threadIdx.x;
    int tx = t & 3, ty = t >> 2;
    int row0 = blockIdx.x * 512;

    if (t < OC_) { sa[t] = as[t]; sd[t] = ad[t]; }
    for (int i = t; i < HC_ * OC_ / 4; i += 256)
        ((float4*)ws)[i] = ((const float4*)W2)[i];

    int rr[4], qq[4], gg[4];
#pragma unroll
    for (int rep = 0; rep < 4; rep++) {
        int idx = t + rep * 256;
        rr[rep] = idx >> 1; qq[rep] = idx & 1; gg[rep] = row0 + rr[rep];
    }
    const float4 z4 = make_float4(0.f, 0.f, 0.f, 0.f);
    float4 pre[4];
#pragma unroll
    for (int rep = 0; rep < 4; rep++)
        pre[rep] = (gg[rep] < NN_) ? ((const float4*)g_h1)[gg[rep] * 16 + qq[rep]] : z4;

    ull acc[4][8];
#pragma unroll
    for (int a = 0; a < 4; a++)
#pragma unroll
        for (int b = 0; b < 8; b++) acc[a][b] = 0ull;

    for (int c = 0; c < 8; c++) {      // 8 chunks of 8 k
        __syncthreads();
#pragma unroll
        for (int rep = 0; rep < 4; rep++) {
            int r = rr[rep], q = qq[rep];
            xs[(4 * q + 0) * XP2_ + r] = pre[rep].x;
            xs[(4 * q + 1) * XP2_ + r] = pre[rep].y;
            xs[(4 * q + 2) * XP2_ + r] = pre[rep].z;
            xs[(4 * q + 3) * XP2_ + r] = pre[rep].w;
        }
        __syncthreads();
        if (c < 7) {
#pragma unroll
            for (int rep = 0; rep < 4; rep++)
                pre[rep] = (gg[rep] < NN_)
                    ? ((const float4*)g_h1)[gg[rep] * 16 + (c + 1) * 2 + qq[rep]] : z4;
        }
#pragma unroll
        for (int k = 0; k < 8; k++) {
            const ull* ap = (const ull*)&xs[k * XP2_ + ty * 8];
            ull a0 = ap[0], a1 = ap[1], a2 = ap[2], a3 = ap[3];
            const float* wr = &ws[(c * 8 + k) * OC_ + tx * 8];
            float4 b0 = *(const float4*)&wr[0];
            float4 b1 = *(const float4*)&wr[4];
            ull p0 = pk2(b0.x, b0.x), p1 = pk2(b0.y, b0.y);
            ull p2 = pk2(b0.z, b0.z), p3 = pk2(b0.w, b0.w);
            ull p4 = pk2(b1.x, b1.x), p5 = pk2(b1.y, b1.y);
            ull p6 = pk2(b1.z, b1.z), p7 = pk2(b1.w, b1.w);
            ull av[4] = {a0, a1, a2, a3};
#pragma unroll
            for (int p = 0; p < 4; p++) {
                ull a = av[p];
                acc[p][0] = f2fma(a, p0, acc[p][0]);
                acc[p][1] = f2fma(a, p1, acc[p][1]);
                acc[p][2] = f2fma(a, p2, acc[p][2]);
                acc[p][3] = f2fma(a, p3, acc[p][3]);
                acc[p][4] = f2fma(a, p4, acc[p][4]);
                acc[p][5] = f2fma(a, p5, acc[p][5]);
                acc[p][6] = f2fma(a, p6, acc[p][6]);
                acc[p][7] = f2fma(a, p7, acc[p][7]);
            }
        }
    }
#pragma unroll
    for (int p = 0; p < 4; p++) {
        float lo[8], hi[8];
#pragma unroll
        for (int cc = 0; cc < 8; cc++) up2(acc[p][cc], lo[cc], hi[cc]);
#pragma unroll
        for (int half = 0; half < 2; half++) {
            const float* v = half ? hi : lo;
            int n = row0 + ty * 8 + 2 * p + half;
            float pas = 0.f, pad = 0.f;
#pragma unroll
            for (int cc = 0; cc < 8; cc++) {
                pas = fmaf(v[cc], sa[tx * 8 + cc], pas);
                pad = fmaf(v[cc], sd[tx * 8 + cc], pad);
            }
            pas += __shfl_xor_sync(0xffffffffu, pas, 1);
            pas += __shfl_xor_sync(0xffffffffu, pas, 2);
            pad += __shfl_xor_sync(0xffffffffu, pad, 1);
            pad += __shfl_xor_sync(0xffffffffu, pad, 2);
            if (n < NN_) {
                *(float4*)&g_xl2[n * OC_ + tx * 8] =
                    make_float4(v[0], v[1], v[2], v[3]);
                *(float4*)&g_xl2[n * OC_ + tx * 8 + 4] =
                    make_float4(v[4], v[5], v[6], v[7]);
                if (tx == 0) { g_as2[n] = pas; g_ad2[n] = pad; }
            }
        }
    }
}

// ---------------- layer-1 aggregation (warp per dst, smem-staged batches) ----
// Lane j coalesced-loads edge record j (MLP=32); per-edge loop reads meta via
// LDS broadcast (29cyc) instead of a serial L2 LDG chain.
__global__ void __launch_bounds__(256, 4)
agg1_kernel(const float* __restrict__ b1) {
    __shared__ float4 stg[8][32];
    int g = blockIdx.x * blockDim.x + threadIdx.x;
    int n = g >> 5, lane = g & 31, wid = (threadIdx.x >> 5);
    if (n >= NN_) return;
    float ex0 = __expf(lrelu(g_as1[n * 2 + 0] + g_ad1[n * 2 + 0]));  // self loop
    float ex1 = __expf(lrelu(g_as1[n * 2 + 1] + g_ad1[n * 2 + 1]));
    float den0 = ex0, den1 = ex1;
    const float2* xl = (const float2*)g_xl1;
    float2 v = xl[n * 32 + lane];
    bool h0 = lane < 16;
    float exm = h0 ? ex0 : ex1;
    float ax = exm * v.x, ay = exm * v.y;
    int st = g_ptr[n], de = g_deg[n];
    for (int base = 0; base < de; base += 32) {
        int m = min(32, de - base);
        if (lane < m) stg[wid][lane] = g_erec[st + base + lane];
        __syncwarp();
#pragma unroll 4
        for (int j = 0; j < m; j++) {
            float4 r = stg[wid][j];              // LDS broadcast
            int s = __float_as_int(r.x);
            den0 += r.y; den1 += r.z;
            float2 w = xl[s * 32 + lane];        // 256B row gather
            float fm = h0 ? r.y : r.z;
            ax = fmaf(fm, w.x, ax);
            ay = fmaf(fm, w.y, ay);
        }
        __syncwarp();
    }
    float den = h0 ? den0 : den1;
    float inv = 1.f / (den + 1e-16f);
    float bx = b1[lane * 2], by = b1[lane * 2 + 1];
    float2 o;
    o.x = fmaxf(fmaf(ax, inv, bx), 0.f);   // bias + ReLU fused
    o.y = fmaxf(fmaf(ay, inv, by), 0.f);
    ((float2*)g_h1)[n * 32 + lane] = o;
}

// ---------------- layer-2 aggregation (exp fused, smem-staged) --------------
// dst == n for every edge in this bin, so lane j computes this edge's
// exp(lrelu(as2[s]+ad2[n])) during staging (lane-parallel MUFU, no kernel).
__global__ void __launch_bounds__(256, 4)
agg2_kernel(const float* __restrict__ b2, float* __restrict__ out) {
    __shared__ float2 stg[8][32];
    int g = blockIdx.x * blockDim.x + threadIdx.x;
    int n = g >> 5, lane = g & 31, wid = (threadIdx.x >> 5);
    if (n >= NN_) return;
    float ad2n = g_ad2[n];
    float ex = __expf(lrelu(g_as2[n] + ad2n));   // self loop
    float den = ex;
    float acc = ex * g_xl2[n * OC_ + lane];
    int st = g_ptr[n], de = g_deg[n];
    for (int base = 0; base < de; base += 32) {
        int m = min(32, de - base);
        if (lane < m) {
            float4 r = g_erec[st + base + lane];
            int s = __float_as_int(r.x);
            float e = __expf(lrelu(g_as2[s] + ad2n));
            stg[wid][lane] = make_float2(r.x, e);
        }
        __syncwarp();
#pragma unroll 4
        for (int j = 0; j < m; j++) {
            float2 r = stg[wid][j];              // LDS broadcast
            int s = __float_as_int(r.x);
            den += r.y;
            acc = fmaf(r.y, g_xl2[s * OC_ + lane], acc);   // 128B row gather
        }
        __syncwarp();
    }
    out[n * OC_ + lane] = acc / (den + 1e-16f) + b2[lane];
}

// ---------------- launch ----------------
extern "C" void kernel_launch(void* const* d_in, const int* in_sizes, int n_in,
                              void* d_out, int out_size) {
    // size-keyed input remap with positional fallback
    const float* x = 0; const int* ei = 0;
    const float* W1 = 0; const float* W2 = 0;
    const float* a64[3] = {0, 0, 0}; int n64 = 0;
    const float* a32[3] = {0, 0, 0}; int n32 = 0;
    for (int i = 0; i < n_in; i++) {
        int sz = in_sizes[i];
        if      (sz == NN_ * INF_) x  = (const float*)d_in[i];
        else if (sz == 2 * NE_)    ei = (const int*)  d_in[i];
        else if (sz == INF_ * HC_) W1 = (const float*)d_in[i];
        else if (sz == HC_ * OC_)  W2 = (const float*)d_in[i];
        else if (sz == HC_) { if (n64 < 3) a64[n64++] = (const float*)d_in[i]; }
        else if (sz == OC_) { if (n32 < 3) a32[n32++] = (const float*)d_in[i]; }
    }
    if (!x)  x  = (const float*)d_in[0];
    if (!ei) ei = (const int*)  d_in[1];
    if (!W1) W1 = (const float*)d_in[2];
    if (!W2) W2 = (const float*)d_in[6];
    const float* as1 = a64[0] ? a64[0] : (const float*)d_in[3];
    const float* ad1 = a64[1] ? a64[1] : (const float*)d_in[4];
    const float* b1  = a64[2] ? a64[2] : (const float*)d_in[5];
    const float* as2 = a32[0] ? a32[0] : (const float*)d_in[7];
    const float* ad2 = a32[1] ? a32[1] : (const float*)d_in[8];
    const float* b2  = a32[2] ? a32[2] : (const float*)d_in[9];
    float* out = (float*)d_out;

    const int* srcp = ei;
    const int* dstp = ei + NE_;

    const int NB  = (NN_ + 255) / 256;         // node blocks
    const int EB  = (NE_ + 255) / 256;         // edge blocks
    const int G1  = (NN_ + 255) / 256;         // 391 gemm1 blocks (256 rows)
    const int G2  = (NN_ + 511) / 512;         // 196 gemm2 blocks (512 rows)
    const int WB  = (NN_ * 32 + 255) / 256;    // 12500 warp-per-node blocks

    prep_kernel<<<NB, 256>>>();
    hist_kernel<<<EB, 256>>>(dstp);
    ptr_kernel<<<NB, 256>>>();

    gemm1_kernel<<<G1, 256>>>(x, W1, as1, ad1);
    scatter_kernel<<<EB, 256>>>(srcp, dstp);
    agg1_kernel<<<WB, 256>>>(b1);

    gemm2_kernel<<<G2, 256>>>(W2, as2, ad2);
    agg2_kernel<<<WB, 256>>>(b2, out);

    (void)n_in; (void)out_size;
}

// round 12
// speedup vs baseline: 1.5343x; 1.0134x over previous
#include <cuda_runtime.h>

#define NN_ 100000
#define NE_ 1600000
#define INF_ 128
#define HC_ 64
#define OC_ 32

// ---------------- scratch (static device globals; no allocation) ----------------
__device__ __align__(16) float  g_xl1[NN_ * HC_];   // x @ W1     (25.6 MB)
__device__ __align__(16) float  g_h1 [NN_ * HC_];   // relu(gat1) (25.6 MB)
__device__ __align__(16) float  g_xl2[NN_ * OC_];   // h @ W2     (12.8 MB)
__device__ float  g_as1[NN_ * 2];                   // layer1 per-node scores
__device__ float  g_ad1[NN_ * 2];
__device__ float  g_as2[NN_];
__device__ float  g_ad2[NN_];
__device__ int    g_deg[NN_];
__device__ int    g_ptr[NN_];
__device__ int    g_cur[NN_];
__device__ int    g_total;
__device__ __align__(16) float4 g_erec[NE_];        // {src, ex0, ex1, -} (25.6 MB)

__device__ __forceinline__ float lrelu(float x) { return x > 0.f ? x : 0.2f * x; }

typedef unsigned long long ull;
__device__ __forceinline__ ull pk2(float x, float y) {
    ull r; asm("mov.b64 %0,{%1,%2};" : "=l"(r) : "f"(x), "f"(y)); return r;
}
__device__ __forceinline__ void up2(ull v, float& x, float& y) {
    asm("mov.b64 {%0,%1},%2;" : "=f"(x), "=f"(y) : "l"(v));
}
// packed fp32x2 FMA (FFMA2): d.lo=fma(a.lo,b.lo,c.lo), d.hi likewise
__device__ __forceinline__ ull f2fma(ull a, ull b, ull c) {
    ull d; asm("fma.rn.f32x2 %0,%1,%2,%3;" : "=l"(d) : "l"(a), "l"(b), "l"(c)); return d;
}

// ---------------- CSR build (no global scans; bins in arbitrary order) -------
__global__ void prep_kernel() {
    int i = blockIdx.x * blockDim.x + threadIdx.x;
    if (i < NN_) g_deg[i] = 0;
    if (i == 0) g_total = 0;
}
__global__ void hist_kernel(const int* __restrict__ dst) {
    int i = blockIdx.x * blockDim.x + threadIdx.x;
    if (i < NE_) atomicAdd(&g_deg[dst[i]], 1);
}
// Hierarchical bin offsets: block-local smem scan + ONE atomic per block.
// (Previous version did 100k atomicAdds on one address: ~0.854 cyc/lane
// serialized at the LTS = ~47us. 391 atomics instead.)
__global__ void ptr_kernel() {
    __shared__ int sdeg[256];
    __shared__ int sbase;
    int t = threadIdx.x;
    int i = blockIdx.x * 256 + t;
    int d = (i < NN_) ? g_deg[i] : 0;
    sdeg[t] = d;
    __syncthreads();
    for (int off = 1; off < 256; off <<= 1) {   // Hillis-Steele inclusive scan
        int u = (t >= off) ? sdeg[t - off] : 0;
        __syncthreads();
        sdeg[t] += u;
        __syncthreads();
    }
    if (t == 255) sbase = atomicAdd(&g_total, sdeg[255]);
    __syncthreads();
    if (i < NN_) {
        int p = sbase + sdeg[t] - d;            // exclusive prefix + block base
        g_ptr[i] = p;
        g_cur[i] = p;                           // scatter cursor starts at bin base
    }
}
// scatter edges into bins; one packed 16B record per edge (1 L2 sector)
__global__ void scatter_kernel(const int* __restrict__ src,
                               const int* __restrict__ dst) {
    int i = blockIdx.x * blockDim.x + threadIdx.x;
    if (i >= NE_) return;
    int s = src[i], d = dst[i];
    int p = atomicAdd(&g_cur[d], 1);
    if (p < 0 || p >= NE_) return;               // defensive: never corrupt memory
    float e0 = g_as1[s * 2 + 0] + g_ad1[d * 2 + 0];
    float e1 = g_as1[s * 2 + 1] + g_ad1[d * 2 + 1];
    g_erec[p] = make_float4(__int_as_float(s),
                            __expf(lrelu(e0)), __expf(lrelu(e1)), 0.f);
}

// ---------------- GEMM1 + scores1 fused (FFMA2, 8x8, reg prefetch) ----------
#define XP_ 260
__global__ void __launch_bounds__(256, 2)
gemm1_kernel(const float* __restrict__ x, const float* __restrict__ W1,
             const float* __restrict__ as, const float* __restrict__ ad) {
    __shared__ float ws[INF_ * HC_];   // 32 KB, [k][c]
    __shared__ float xs[8 * XP_];      // 8.3 KB, [k_local][row(padded)]
    __shared__ float sa[HC_], sd[HC_];
    int t = threadIdx.x;
    int tx = t & 7, ty = t >> 3;
    int row0 = blockIdx.x * 256;

    if (t < HC_) { sa[t] = as[t]; sd[t] = ad[t]; }
    for (int i = t; i < INF_ * HC_ / 4; i += 256)
        ((float4*)ws)[i] = ((const float4*)W1)[i];

    int r0 = t >> 1,          q0 = t & 1;
    int r1 = (t + 256) >> 1,  q1 = (t + 256) & 1;
    int gr0 = row0 + r0, gr1 = row0 + r1;
    const float4 z4 = make_float4(0.f, 0.f, 0.f, 0.f);

    float4 pre0 = (gr0 < NN_) ? ((const float4*)x)[gr0 * 32 + q0] : z4;
    float4 pre1 = (gr1 < NN_) ? ((const float4*)x)[gr1 * 32 + q1] : z4;

    ull acc[4][8];                     // [row-pair][col]
#pragma unroll
    for (int a = 0; a < 4; a++)
#pragma unroll
        for (int b = 0; b < 8; b++) acc[a][b] = 0ull;

    for (int c = 0; c < 16; c++) {     // 16 chunks of 8 k
        __syncthreads();
        xs[(4 * q0 + 0) * XP_ + r0] = pre0.x;
        xs[(4 * q0 + 1) * XP_ + r0] = pre0.y;
        xs[(4 * q0 + 2) * XP_ + r0] = pre0.z;
        xs[(4 * q0 + 3) * XP_ + r0] = pre0.w;
        xs[(4 * q1 + 0) * XP_ + r1] = pre1.x;
        xs[(4 * q1 + 1) * XP_ + r1] = pre1.y;
        xs[(4 * q1 + 2) * XP_ + r1] = pre1.z;
        xs[(4 * q1 + 3) * XP_ + r1] = pre1.w;
        __syncthreads();
        if (c < 15) {
            pre0 = (gr0 < NN_) ? ((const float4*)x)[gr0 * 32 + (c + 1) * 2 + q0] : z4;
            pre1 = (gr1 < NN_) ? ((const float4*)x)[gr1 * 32 + (c + 1) * 2 + q1] : z4;
        }
#pragma unroll
        for (int k = 0; k < 8; k++) {
            const ull* ap = (const ull*)&xs[k * XP_ + ty * 8];
            ull a0 = ap[0], a1 = ap[1], a2 = ap[2], a3 = ap[3];
            const float* wr = &ws[(c * 8 + k) * HC_ + tx * 8];
            float4 b0 = *(const float4*)&wr[0];
            float4 b1 = *(const float4*)&wr[4];
            ull p0 = pk2(b0.x, b0.x), p1 = pk2(b0.y, b0.y);
            ull p2 = pk2(b0.z, b0.z), p3 = pk2(b0.w, b0.w);
            ull p4 = pk2(b1.x, b1.x), p5 = pk2(b1.y, b1.y);
            ull p6 = pk2(b1.z, b1.z), p7 = pk2(b1.w, b1.w);
            ull av[4] = {a0, a1, a2, a3};
#pragma unroll
            for (int p = 0; p < 4; p++) {
                ull a = av[p];
                acc[p][0] = f2fma(a, p0, acc[p][0]);
                acc[p][1] = f2fma(a, p1, acc[p][1]);
                acc[p][2] = f2fma(a, p2, acc[p][2]);
                acc[p][3] = f2fma(a, p3, acc[p][3]);
                acc[p][4] = f2fma(a, p4, acc[p][4]);
                acc[p][5] = f2fma(a, p5, acc[p][5]);
                acc[p][6] = f2fma(a, p6, acc[p][6]);
                acc[p][7] = f2fma(a, p7, acc[p][7]);
            }
        }
    }
#pragma unroll
    for (int p = 0; p < 4; p++) {
        float lo[8], hi[8];
#pragma unroll
        for (int cc = 0; cc < 8; cc++) up2(acc[p][cc], lo[cc], hi[cc]);
#pragma unroll
        for (int half = 0; half < 2; half++) {
            const float* v = half ? hi : lo;
            int n = row0 + ty * 8 + 2 * p + half;
            float pas = 0.f, pad = 0.f;
#pragma unroll
            for (int cc = 0; cc < 8; cc++) {
                pas = fmaf(v[cc], sa[tx * 8 + cc], pas);
                pad = fmaf(v[cc], sd[tx * 8 + cc], pad);
            }
            pas += __shfl_xor_sync(0xffffffffu, pas, 1);
            pas += __shfl_xor_sync(0xffffffffu, pas, 2);
            pad += __shfl_xor_sync(0xffffffffu, pad, 1);
            pad += __shfl_xor_sync(0xffffffffu, pad, 2);
            if (n < NN_) {
                *(float4*)&g_xl1[n * HC_ + tx * 8] =
                    make_float4(v[0], v[1], v[2], v[3]);
                *(float4*)&g_xl1[n * HC_ + tx * 8 + 4] =
                    make_float4(v[4], v[5], v[6], v[7]);
                if (tx == 0 || tx == 4) {
                    int h = tx >> 2;
                    g_as1[n * 2 + h] = pas;
                    g_ad1[n * 2 + h] = pad;
                }
            }
        }
    }
}

// ---------------- GEMM2 + scores2 fused (FFMA2, 8x8, BM=512) ----------------
#define XP2_ 516
__global__ void __launch_bounds__(256, 2)
gemm2_kernel(const float* __restrict__ W2,
             const float* __restrict__ as, const float* __restrict__ ad) {
    __shared__ float ws[HC_ * OC_];    //  8 KB, [k][c]
    __shared__ float xs[8 * XP2_];     // 16.5 KB, [k_local][row(padded)]
    __shared__ float sa[OC_], sd[OC_];
    int t = threadIdx.x;
    int tx = t & 3, ty = t >> 2;
    int row0 = blockIdx.x * 512;

    if (t < OC_) { sa[t] = as[t]; sd[t] = ad[t]; }
    for (int i = t; i < HC_ * OC_ / 4; i += 256)
        ((float4*)ws)[i] = ((const float4*)W2)[i];

    int rr[4], qq[4], gg[4];
#pragma unroll
    for (int rep = 0; rep < 4; rep++) {
        int idx = t + rep * 256;
        rr[rep] = idx >> 1; qq[rep] = idx & 1; gg[rep] = row0 + rr[rep];
    }
    const float4 z4 = make_float4(0.f, 0.f, 0.f, 0.f);
    float4 pre[4];
#pragma unroll
    for (int rep = 0; rep < 4; rep++)
        pre[rep] = (gg[rep] < NN_) ? ((const float4*)g_h1)[gg[rep] * 16 + qq[rep]] : z4;

    ull acc[4][8];
#pragma unroll
    for (int a = 0; a < 4; a++)
#pragma unroll
        for (int b = 0; b < 8; b++) acc[a][b] = 0ull;

    for (int c = 0; c < 8; c++) {      // 8 chunks of 8 k
        __syncthreads();
#pragma unroll
        for (int rep = 0; rep < 4; rep++) {
            int r = rr[rep], q = qq[rep];
            xs[(4 * q + 0) * XP2_ + r] = pre[rep].x;
            xs[(4 * q + 1) * XP2_ + r] = pre[rep].y;
            xs[(4 * q + 2) * XP2_ + r] = pre[rep].z;
            xs[(4 * q + 3) * XP2_ + r] = pre[rep].w;
        }
        __syncthreads();
        if (c < 7) {
#pragma unroll
            for (int rep = 0; rep < 4; rep++)
                pre[rep] = (gg[rep] < NN_)
                    ? ((const float4*)g_h1)[gg[rep] * 16 + (c + 1) * 2 + qq[rep]] : z4;
        }
#pragma unroll
        for (int k = 0; k < 8; k++) {
            const ull* ap = (const ull*)&xs[k * XP2_ + ty * 8];
            ull a0 = ap[0], a1 = ap[1], a2 = ap[2], a3 = ap[3];
            const float* wr = &ws[(c * 8 + k) * OC_ + tx * 8];
            float4 b0 = *(const float4*)&wr[0];
            float4 b1 = *(const float4*)&wr[4];
            ull p0 = pk2(b0.x, b0.x), p1 = pk2(b0.y, b0.y);
            ull p2 = pk2(b0.z, b0.z), p3 = pk2(b0.w, b0.w);
            ull p4 = pk2(b1.x, b1.x), p5 = pk2(b1.y, b1.y);
            ull p6 = pk2(b1.z, b1.z), p7 = pk2(b1.w, b1.w);
            ull av[4] = {a0, a1, a2, a3};
#pragma unroll
            for (int p = 0; p < 4; p++) {
                ull a = av[p];
                acc[p][0] = f2fma(a, p0, acc[p][0]);
                acc[p][1] = f2fma(a, p1, acc[p][1]);
                acc[p][2] = f2fma(a, p2, acc[p][2]);
                acc[p][3] = f2fma(a, p3, acc[p][3]);
                acc[p][4] = f2fma(a, p4, acc[p][4]);
                acc[p][5] = f2fma(a, p5, acc[p][5]);
                acc[p][6] = f2fma(a, p6, acc[p][6]);
                acc[p][7] = f2fma(a, p7, acc[p][7]);
            }
        }
    }
#pragma unroll
    for (int p = 0; p < 4; p++) {
        float lo[8], hi[8];
#pragma unroll
        for (int cc = 0; cc < 8; cc++) up2(acc[p][cc], lo[cc], hi[cc]);
#pragma unroll
        for (int half = 0; half < 2; half++) {
            const float* v = half ? hi : lo;
            int n = row0 + ty * 8 + 2 * p + half;
            float pas = 0.f, pad = 0.f;
#pragma unroll
            for (int cc = 0; cc < 8; cc++) {
                pas = fmaf(v[cc], sa[tx * 8 + cc], pas);
                pad = fmaf(v[cc], sd[tx * 8 + cc], pad);
            }
            pas += __shfl_xor_sync(0xffffffffu, pas, 1);
            pas += __shfl_xor_sync(0xffffffffu, pas, 2);
            pad += __shfl_xor_sync(0xffffffffu, pad, 1);
            pad += __shfl_xor_sync(0xffffffffu, pad, 2);
            if (n < NN_) {
                *(float4*)&g_xl2[n * OC_ + tx * 8] =
                    make_float4(v[0], v[1], v[2], v[3]);
                *(float4*)&g_xl2[n * OC_ + tx * 8 + 4] =
                    make_float4(v[4], v[5], v[6], v[7]);
                if (tx == 0) { g_as2[n] = pas; g_ad2[n] = pad; }
            }
        }
    }
}

// ---------------- layer-1 aggregation (warp per dst, smem-staged batches) ----
__global__ void __launch_bounds__(256, 4)
agg1_kernel(const float* __restrict__ b1) {
    __shared__ float4 stg[8][32];
    int g = blockIdx.x * blockDim.x + threadIdx.x;
    int n = g >> 5, lane = g & 31, wid = (threadIdx.x >> 5);
    if (n >= NN_) return;
    float ex0 = __expf(lrelu(g_as1[n * 2 + 0] + g_ad1[n * 2 + 0]));  // self loop
    float ex1 = __expf(lrelu(g_as1[n * 2 + 1] + g_ad1[n * 2 + 1]));
    float den0 = ex0, den1 = ex1;
    const float2* xl = (const float2*)g_xl1;
    float2 v = xl[n * 32 + lane];
    bool h0 = lane < 16;
    float exm = h0 ? ex0 : ex1;
    float ax = exm * v.x, ay = exm * v.y;
    int st = g_ptr[n], de = g_deg[n];
    for (int base = 0; base < de; base += 32) {
        int m = min(32, de - base);
        if (lane < m) stg[wid][lane] = g_erec[st + base + lane];
        __syncwarp();
#pragma unroll 4
        for (int j = 0; j < m; j++) {
            float4 r = stg[wid][j];              // LDS broadcast
            int s = __float_as_int(r.x);
            den0 += r.y; den1 += r.z;
            float2 w = xl[s * 32 + lane];        // 256B row gather
            float fm = h0 ? r.y : r.z;
            ax = fmaf(fm, w.x, ax);
            ay = fmaf(fm, w.y, ay);
        }
        __syncwarp();
    }
    float den = h0 ? den0 : den1;
    float inv = 1.f / (den + 1e-16f);
    float bx = b1[lane * 2], by = b1[lane * 2 + 1];
    float2 o;
    o.x = fmaxf(fmaf(ax, inv, bx), 0.f);   // bias + ReLU fused
    o.y = fmaxf(fmaf(ay, inv, by), 0.f);
    ((float2*)g_h1)[n * 32 + lane] = o;
}

// ---------------- layer-2 aggregation (exp fused, smem-staged) --------------
__global__ void __launch_bounds__(256, 4)
agg2_kernel(const float* __restrict__ b2, float* __restrict__ out) {
    __shared__ float2 stg[8][32];
    int g = blockIdx.x * blockDim.x + threadIdx.x;
    int n = g >> 5, lane = g & 31, wid = (threadIdx.x >> 5);
    if (n >= NN_) return;
    float ad2n = g_ad2[n];
    float ex = __expf(lrelu(g_as2[n] + ad2n));   // self loop
    float den = ex;
    float acc = ex * g_xl2[n * OC_ + lane];
    int st = g_ptr[n], de = g_deg[n];
    for (int base = 0; base < de; base += 32) {
        int m = min(32, de - base);
        if (lane < m) {
            float4 r = g_erec[st + base + lane];
            int s = __float_as_int(r.x);
            float e = __expf(lrelu(g_as2[s] + ad2n));
            stg[wid][lane] = make_float2(r.x, e);
        }
        __syncwarp();
#pragma unroll 4
        for (int j = 0; j < m; j++) {
            float2 r = stg[wid][j];              // LDS broadcast
            int s = __float_as_int(r.x);
            den += r.y;
            acc = fmaf(r.y, g_xl2[s * OC_ + lane], acc);   // 128B row gather
        }
        __syncwarp();
    }
    out[n * OC_ + lane] = acc / (den + 1e-16f) + b2[lane];
}

// ---------------- launch ----------------
extern "C" void kernel_launch(void* const* d_in, const int* in_sizes, int n_in,
                              void* d_out, int out_size) {
    // size-keyed input remap with positional fallback
    const float* x = 0; const int* ei = 0;
    const float* W1 = 0; const float* W2 = 0;
    const float* a64[3] = {0, 0, 0}; int n64 = 0;
    const float* a32[3] = {0, 0, 0}; int n32 = 0;
    for (int i = 0; i < n_in; i++) {
        int sz = in_sizes[i];
        if      (sz == NN_ * INF_) x  = (const float*)d_in[i];
        else if (sz == 2 * NE_)    ei = (const int*)  d_in[i];
        else if (sz == INF_ * HC_) W1 = (const float*)d_in[i];
        else if (sz == HC_ * OC_)  W2 = (const float*)d_in[i];
        else if (sz == HC_) { if (n64 < 3) a64[n64++] = (const float*)d_in[i]; }
        else if (sz == OC_) { if (n32 < 3) a32[n32++] = (const float*)d_in[i]; }
    }
    if (!x)  x  = (const float*)d_in[0];
    if (!ei) ei = (const int*)  d_in[1];
    if (!W1) W1 = (const float*)d_in[2];
    if (!W2) W2 = (const float*)d_in[6];
    const float* as1 = a64[0] ? a64[0] : (const float*)d_in[3];
    const float* ad1 = a64[1] ? a64[1] : (const float*)d_in[4];
    const float* b1  = a64[2] ? a64[2] : (const float*)d_in[5];
    const float* as2 = a32[0] ? a32[0] : (const float*)d_in[7];
    const float* ad2 = a32[1] ? a32[1] : (const float*)d_in[8];
    const float* b2  = a32[2] ? a32[2] : (const float*)d_in[9];
    float* out = (float*)d_out;

    const int* srcp = ei;
    const int* dstp = ei + NE_;

    const int NB  = (NN_ + 255) / 256;         // node blocks
    const int EB  = (NE_ + 255) / 256;         // edge blocks
    const int G1  = (NN_ + 255) / 256;         // 391 gemm1 blocks (256 rows)
    const int G2  = (NN_ + 511) / 512;         // 196 gemm2 blocks (512 rows)
    const int WB  = (NN_ * 32 + 255) / 256;    // 12500 warp-per-node blocks

    prep_kernel<<<NB, 256>>>();
    hist_kernel<<<EB, 256>>>(dstp);
    ptr_kernel<<<NB, 256>>>();

    gemm1_kernel<<<G1, 256>>>(x, W1, as1, ad1);
    scatter_kernel<<<EB, 256>>>(srcp, dstp);
    agg1_kernel<<<WB, 256>>>(b1);

    gemm2_kernel<<<G2, 256>>>(W2, as2, ad2);
    agg2_kernel<<<WB, 256>>>(b2, out);

    (void)n_in; (void)out_size;
}